// round 1
// baseline (speedup 1.0000x reference)
#include <cuda_runtime.h>
#include <cuda_bf16.h>
#include <math.h>

// Problem constants
#define B_  4
#define S_  2048
#define H_  1024
#define NH_ 16
#define HD_ 64
#define M_  (B_ * S_)      // 8192 rows for all projections
#define K_  1024
#define N_  1024

// Scratch (device globals: allocation-free per harness rules)
__device__ float g_q[B_ * S_ * H_];    // [B,NH,S,HD]
__device__ float g_k[B_ * S_ * H_];    // [B,NH,S,HD]
__device__ float g_v[B_ * S_ * H_];    // [B,NH,S,HD]
__device__ float g_ctx[B_ * S_ * H_];  // [B,S,H]

// ----------------------------------------------------------------------------
// GEMM: C[row][col] = sum_k A[row][k] * W[col][k] + bias[col]
// A: [M,K] row-major, W: [N,K] row-major (i.e. computes A @ W^T + b)
// SCATTER=1: write into [B,NH,S,HD] layout (row=b*S+s, col=h*HD+d)
// Tiling: 128x128x8, 256 threads, 8x8 microtile (split as 2x2 of 4-wide chunks)
// ----------------------------------------------------------------------------
template <int SCATTER>
__global__ __launch_bounds__(256, 2)
void gemm_kernel(const float* __restrict__ A, const float* __restrict__ W,
                 const float* __restrict__ bias, float* __restrict__ C) {
    __shared__ float As[8][132];   // [k][m], pad 132 -> conflict-free
    __shared__ float Ws[8][132];   // [k][n]

    const int t  = threadIdx.x;
    const int tx = t & 15;
    const int ty = t >> 4;
    const int row0 = blockIdx.y * 128;
    const int col0 = blockIdx.x * 128;

    // load mapping: each thread fetches one float4 of A and of W per k-tile
    const int lr = t >> 1;          // 0..127 row (A) / col (W) within tile
    const int lk = (t & 1) << 2;    // 0 or 4
    const float* Ap = A + (size_t)(row0 + lr) * K_ + lk;
    const float* Wp = W + (size_t)(col0 + lr) * K_ + lk;

    float acc[8][8];
#pragma unroll
    for (int i = 0; i < 8; i++)
#pragma unroll
        for (int j = 0; j < 8; j++) acc[i][j] = 0.f;

    for (int k0 = 0; k0 < K_; k0 += 8) {
        float4 av = *(const float4*)(Ap + k0);
        float4 wv = *(const float4*)(Wp + k0);
        __syncthreads();
        As[lk + 0][lr] = av.x; As[lk + 1][lr] = av.y;
        As[lk + 2][lr] = av.z; As[lk + 3][lr] = av.w;
        Ws[lk + 0][lr] = wv.x; Ws[lk + 1][lr] = wv.y;
        Ws[lk + 2][lr] = wv.z; Ws[lk + 3][lr] = wv.w;
        __syncthreads();
#pragma unroll
        for (int kk = 0; kk < 8; kk++) {
            float a[8], b[8];
            float4 a0 = *(const float4*)&As[kk][4 * ty];
            float4 a1 = *(const float4*)&As[kk][64 + 4 * ty];
            float4 b0 = *(const float4*)&Ws[kk][4 * tx];
            float4 b1 = *(const float4*)&Ws[kk][64 + 4 * tx];
            a[0]=a0.x; a[1]=a0.y; a[2]=a0.z; a[3]=a0.w;
            a[4]=a1.x; a[5]=a1.y; a[6]=a1.z; a[7]=a1.w;
            b[0]=b0.x; b[1]=b0.y; b[2]=b0.z; b[3]=b0.w;
            b[4]=b1.x; b[5]=b1.y; b[6]=b1.z; b[7]=b1.w;
#pragma unroll
            for (int i = 0; i < 8; i++)
#pragma unroll
                for (int j = 0; j < 8; j++)
                    acc[i][j] = fmaf(a[i], b[j], acc[i][j]);
        }
    }

    // epilogue
#pragma unroll
    for (int ih = 0; ih < 2; ih++) {
#pragma unroll
        for (int i = 0; i < 4; i++) {
            const int row = row0 + ih * 64 + 4 * ty + i;
#pragma unroll
            for (int jh = 0; jh < 2; jh++) {
                const int col = col0 + jh * 64 + 4 * tx;
                float4 v;
                v.x = acc[ih * 4 + i][jh * 4 + 0] + bias[col + 0];
                v.y = acc[ih * 4 + i][jh * 4 + 1] + bias[col + 1];
                v.z = acc[ih * 4 + i][jh * 4 + 2] + bias[col + 2];
                v.w = acc[ih * 4 + i][jh * 4 + 3] + bias[col + 3];
                if (SCATTER) {
                    const int bb = row >> 11;      // row / S
                    const int ss = row & 2047;     // row % S
                    const int hh = col >> 6;       // col / HD
                    const int dd = col & 63;       // col % HD
                    *(float4*)&C[(((size_t)(bb * NH_ + hh) * S_) + ss) * HD_ + dd] = v;
                } else {
                    *(float4*)&C[(size_t)row * N_ + col] = v;
                }
            }
        }
    }
}

// ----------------------------------------------------------------------------
// Flash attention (fp32, online softmax).
// Block: (b, h, 64 q-rows). 256 threads as 16x16: thread owns 4 q-rows x 4 cols.
// Smem: Qs[64][68] (q x d), KPs[64][68] (K transposed [d][kv], reused as P[q][kv]),
//       Vs[64][68] (kv x d). Stride 68 floats = 17*16B (odd multiple of 16B).
// ----------------------------------------------------------------------------
#define ATTN_SMEM (3 * 64 * 68 * 4)

__global__ __launch_bounds__(256)
void flash_attn_kernel(const float* __restrict__ Q, const float* __restrict__ Kk,
                       const float* __restrict__ V, const float* __restrict__ amask,
                       float* __restrict__ ctx) {
    extern __shared__ float sm[];
    float (*Qs)[68]  = (float(*)[68])(sm);
    float (*KPs)[68] = (float(*)[68])(sm + 64 * 68);
    float (*Vs)[68]  = (float(*)[68])(sm + 2 * 64 * 68);

    const int t  = threadIdx.x;
    const int tx = t & 15;
    const int ty = t >> 4;
    const int b  = blockIdx.z;
    const int h  = blockIdx.y;
    const int q0 = blockIdx.x * 64;

    const float* qb = Q  + ((size_t)(b * NH_ + h) * S_ + q0) * HD_;
    const float* kb = Kk + ((size_t)(b * NH_ + h) * S_) * HD_;
    const float* vb = V  + ((size_t)(b * NH_ + h) * S_) * HD_;
    const float* mb = amask + (size_t)b * S_;

    // Load Q tile [64 x 64], coalesced float4
#pragma unroll
    for (int i = 0; i < 4; i++) {
        const int idx = t + i * 256;
        const int r = idx >> 4;
        const int d4 = (idx & 15) << 2;
        *(float4*)&Qs[r][d4] = *(const float4*)(qb + r * HD_ + d4);
    }

    float m_i[4], l_i[4], acc[4][4];
#pragma unroll
    for (int i = 0; i < 4; i++) {
        m_i[i] = -1e30f;
        l_i[i] = 0.f;
#pragma unroll
        for (int j = 0; j < 4; j++) acc[i][j] = 0.f;
    }

    for (int kv0 = 0; kv0 < S_; kv0 += 64) {
        __syncthreads();  // previous P@V done before overwriting KPs/Vs
        // Load K transposed into KPs[d][kv] (conflict-free stores: lanes span rows),
        // and V straight into Vs[kv][d] (coalesced).
#pragma unroll
        for (int i = 0; i < 4; i++) {
            const int idx = t + i * 256;
            const int r  = idx & 63;
            const int c4 = idx >> 6;           // 0..15 (d chunk)
            float4 kvv = *(const float4*)(kb + (size_t)(kv0 + r) * HD_ + c4 * 4);
            KPs[c4 * 4 + 0][r] = kvv.x;
            KPs[c4 * 4 + 1][r] = kvv.y;
            KPs[c4 * 4 + 2][r] = kvv.z;
            KPs[c4 * 4 + 3][r] = kvv.w;
            const int r2 = idx >> 4;
            const int d4 = (idx & 15) << 2;
            *(float4*)&Vs[r2][d4] = *(const float4*)(vb + (size_t)(kv0 + r2) * HD_ + d4);
        }
        __syncthreads();

        float madd[4];
#pragma unroll
        for (int j = 0; j < 4; j++)
            madd[j] = (1.0f - mb[kv0 + 4 * tx + j]) * -10000.0f;

        // S = Q @ K^T for this tile: s[i][j], rows 4ty+i, kv cols 4tx+j
        float s[4][4];
#pragma unroll
        for (int i = 0; i < 4; i++)
#pragma unroll
            for (int j = 0; j < 4; j++) s[i][j] = 0.f;

#pragma unroll
        for (int d = 0; d < 64; d += 4) {
            float qf[4][4], kf[4][4];
#pragma unroll
            for (int i = 0; i < 4; i++) {
                float4 qq = *(const float4*)&Qs[4 * ty + i][d];
                qf[i][0] = qq.x; qf[i][1] = qq.y; qf[i][2] = qq.z; qf[i][3] = qq.w;
            }
#pragma unroll
            for (int u = 0; u < 4; u++) {
                float4 kk = *(const float4*)&KPs[d + u][4 * tx];
                kf[u][0] = kk.x; kf[u][1] = kk.y; kf[u][2] = kk.z; kf[u][3] = kk.w;
            }
#pragma unroll
            for (int i = 0; i < 4; i++)
#pragma unroll
                for (int u = 0; u < 4; u++)
#pragma unroll
                    for (int j = 0; j < 4; j++)
                        s[i][j] = fmaf(qf[i][u], kf[u][j], s[i][j]);
        }

        // Online softmax update. Row group = 16 contiguous half-warp lanes.
#pragma unroll
        for (int i = 0; i < 4; i++) {
            float rmax = -1e30f;
#pragma unroll
            for (int j = 0; j < 4; j++) {
                s[i][j] = s[i][j] * 0.125f + madd[j];   // 1/sqrt(64)=0.125
                rmax = fmaxf(rmax, s[i][j]);
            }
#pragma unroll
            for (int o = 1; o < 16; o <<= 1)
                rmax = fmaxf(rmax, __shfl_xor_sync(0xffffffffu, rmax, o));
            const float m_new = fmaxf(m_i[i], rmax);
            const float corr  = __expf(m_i[i] - m_new);
            float rs = 0.f;
#pragma unroll
            for (int j = 0; j < 4; j++) {
                s[i][j] = __expf(s[i][j] - m_new);
                rs += s[i][j];
            }
#pragma unroll
            for (int o = 1; o < 16; o <<= 1)
                rs += __shfl_xor_sync(0xffffffffu, rs, o);
            l_i[i] = l_i[i] * corr + rs;
            m_i[i] = m_new;
#pragma unroll
            for (int j = 0; j < 4; j++) acc[i][j] *= corr;
        }

        // Write P into KPs (reuse), then acc += P @ V
        __syncthreads();
#pragma unroll
        for (int i = 0; i < 4; i++)
            *(float4*)&KPs[4 * ty + i][4 * tx] =
                make_float4(s[i][0], s[i][1], s[i][2], s[i][3]);
        __syncthreads();

#pragma unroll
        for (int kc = 0; kc < 64; kc += 4) {
            float pf[4][4], vf[4][4];
#pragma unroll
            for (int i = 0; i < 4; i++) {
                float4 pp = *(const float4*)&KPs[4 * ty + i][kc];
                pf[i][0] = pp.x; pf[i][1] = pp.y; pf[i][2] = pp.z; pf[i][3] = pp.w;
            }
#pragma unroll
            for (int u = 0; u < 4; u++) {
                float4 vv = *(const float4*)&Vs[kc + u][4 * tx];
                vf[u][0] = vv.x; vf[u][1] = vv.y; vf[u][2] = vv.z; vf[u][3] = vv.w;
            }
#pragma unroll
            for (int i = 0; i < 4; i++)
#pragma unroll
                for (int u = 0; u < 4; u++)
#pragma unroll
                    for (int j = 0; j < 4; j++)
                        acc[i][j] = fmaf(pf[i][u], vf[u][j], acc[i][j]);
        }
    }

    // Epilogue: ctx[b][row][h*HD + col] = acc / l
#pragma unroll
    for (int i = 0; i < 4; i++) {
        const float inv = 1.0f / l_i[i];
        const int row = q0 + 4 * ty + i;
        float4 v = make_float4(acc[i][0] * inv, acc[i][1] * inv,
                               acc[i][2] * inv, acc[i][3] * inv);
        *(float4*)&ctx[((size_t)b * S_ + row) * H_ + h * HD_ + 4 * tx] = v;
    }
}

// ----------------------------------------------------------------------------
extern "C" void kernel_launch(void* const* d_in, const int* in_sizes, int n_in,
                              void* d_out, int out_size) {
    const float* query = (const float*)d_in[0];
    const float* key_  = (const float*)d_in[1];
    const float* value = (const float*)d_in[2];
    const float* amask = (const float*)d_in[3];
    const float* Wq = (const float*)d_in[4];
    const float* bq = (const float*)d_in[5];
    const float* Wk = (const float*)d_in[6];
    const float* bk = (const float*)d_in[7];
    const float* Wv = (const float*)d_in[8];
    const float* bv = (const float*)d_in[9];
    const float* Wo = (const float*)d_in[10];
    const float* bo = (const float*)d_in[11];
    float* out = (float*)d_out;

    float *qp, *kp, *vp, *cp;
    cudaGetSymbolAddress((void**)&qp, g_q);
    cudaGetSymbolAddress((void**)&kp, g_k);
    cudaGetSymbolAddress((void**)&vp, g_v);
    cudaGetSymbolAddress((void**)&cp, g_ctx);

    cudaFuncSetAttribute(flash_attn_kernel,
                         cudaFuncAttributeMaxDynamicSharedMemorySize, ATTN_SMEM);

    dim3 gblk(256);
    dim3 ggrid(N_ / 128, M_ / 128);   // (8, 64)

    gemm_kernel<1><<<ggrid, gblk>>>(query, Wq, bq, qp);
    gemm_kernel<1><<<ggrid, gblk>>>(key_,  Wk, bk, kp);
    gemm_kernel<1><<<ggrid, gblk>>>(value, Wv, bv, vp);

    flash_attn_kernel<<<dim3(S_ / 64, NH_, B_), 256, ATTN_SMEM>>>(qp, kp, vp, amask, cp);

    gemm_kernel<0><<<ggrid, gblk>>>(cp, Wo, bo, out);
}

// round 2
// speedup vs baseline: 2.4092x; 2.4092x over previous
#include <cuda_runtime.h>
#include <cuda_bf16.h>
#include <math.h>
#include <stdint.h>

// Problem constants
#define B_  4
#define S_  2048
#define H_  1024
#define NH_ 16
#define HD_ 64
#define M_  (B_ * S_)
#define K_  1024
#define N_  1024

// Scratch (device globals: allocation-free per harness rules)
__device__ float g_q[B_ * S_ * H_];    // [B,NH,S,HD]
__device__ float g_k[B_ * S_ * H_];    // [B,NH,S,HD]
__device__ float g_v[B_ * S_ * H_];    // [B,NH,S,HD]
__device__ float g_ctx[B_ * S_ * H_];  // [B,S,H]

// ---------------------------------------------------------------------------
// tf32 helpers
// ---------------------------------------------------------------------------
__device__ __forceinline__ uint32_t f2tf(float f) {
    uint32_t u;
    asm("cvt.rna.tf32.f32 %0, %1;" : "=r"(u) : "f"(f));
    return u;
}

__device__ __forceinline__ void mma_tf32(float c[4],
                                         uint32_t a0, uint32_t a1,
                                         uint32_t a2, uint32_t a3,
                                         uint32_t b0, uint32_t b1) {
    asm volatile(
        "mma.sync.aligned.m16n8k8.row.col.f32.tf32.tf32.f32 "
        "{%0,%1,%2,%3},{%4,%5,%6,%7},{%8,%9},{%0,%1,%2,%3};"
        : "+f"(c[0]), "+f"(c[1]), "+f"(c[2]), "+f"(c[3])
        : "r"(a0), "r"(a1), "r"(a2), "r"(a3), "r"(b0), "r"(b1));
}

// ---------------------------------------------------------------------------
// GEMM: C = A @ W^T + bias.  A:[M,K] row-major, W:[N,K] row-major.
// tf32 tensor-core path. 128x128 tile, BK=16, 256 threads (8 warps),
// warp tile 64x32 (4 m-tiles x 4 n-tiles of m16n8k8).
// SCATTER=1: write into [B,NH,S,HD].
// ---------------------------------------------------------------------------
template <int SCATTER>
__global__ __launch_bounds__(256)
void gemm_tc(const float* __restrict__ A, const float* __restrict__ W,
             const float* __restrict__ bias, float* __restrict__ C) {
    __shared__ uint32_t As[128][20];   // [m][k], pad 20 -> frag reads conflict-free
    __shared__ uint32_t Ws[128][20];   // [n][k]

    const int t    = threadIdx.x;
    const int warp = t >> 5;
    const int lane = t & 31;
    const int g    = lane >> 2;        // groupID 0..7
    const int tig  = lane & 3;         // threadInGroup 0..3
    const int wm   = (warp & 1) * 64;  // warp m offset
    const int wn   = (warp >> 1) * 32; // warp n offset
    const int row0 = blockIdx.y * 128;
    const int col0 = blockIdx.x * 128;

    // staging: 128 rows x 16 k per tile = 512 float4 loads, 2 per thread
    int   sr[2], sc[2];
    sr[0] = t >> 2;          sc[0] = (t & 3) * 4;
    sr[1] = (t + 256) >> 2;  sc[1] = ((t + 256) & 3) * 4;

    const float* Ap = A + (size_t)(row0)*K_;
    const float* Wp = W + (size_t)(col0)*K_;

    float acc[4][4][4];
#pragma unroll
    for (int i = 0; i < 4; i++)
#pragma unroll
        for (int j = 0; j < 4; j++)
#pragma unroll
            for (int r = 0; r < 4; r++) acc[i][j][r] = 0.f;

    float4 pa[2], pw[2];
#pragma unroll
    for (int i = 0; i < 2; i++) {
        pa[i] = *(const float4*)(Ap + (size_t)sr[i] * K_ + sc[i]);
        pw[i] = *(const float4*)(Wp + (size_t)sr[i] * K_ + sc[i]);
    }

    for (int k0 = 0; k0 < K_; k0 += 16) {
        __syncthreads();
#pragma unroll
        for (int i = 0; i < 2; i++) {
            uint4 ua = make_uint4(f2tf(pa[i].x), f2tf(pa[i].y), f2tf(pa[i].z), f2tf(pa[i].w));
            uint4 uw = make_uint4(f2tf(pw[i].x), f2tf(pw[i].y), f2tf(pw[i].z), f2tf(pw[i].w));
            *(uint4*)&As[sr[i]][sc[i]] = ua;
            *(uint4*)&Ws[sr[i]][sc[i]] = uw;
        }
        __syncthreads();

        if (k0 + 16 < K_) {
#pragma unroll
            for (int i = 0; i < 2; i++) {
                pa[i] = *(const float4*)(Ap + (size_t)sr[i] * K_ + k0 + 16 + sc[i]);
                pw[i] = *(const float4*)(Wp + (size_t)sr[i] * K_ + k0 + 16 + sc[i]);
            }
        }

#pragma unroll
        for (int kk = 0; kk < 16; kk += 8) {
            uint32_t af[4][4], bf[4][2];
#pragma unroll
            for (int mt = 0; mt < 4; mt++) {
                const int mr = wm + mt * 16;
                af[mt][0] = As[mr + g][kk + tig];
                af[mt][1] = As[mr + g + 8][kk + tig];
                af[mt][2] = As[mr + g][kk + tig + 4];
                af[mt][3] = As[mr + g + 8][kk + tig + 4];
            }
#pragma unroll
            for (int nt = 0; nt < 4; nt++) {
                const int nr = wn + nt * 8;
                bf[nt][0] = Ws[nr + g][kk + tig];
                bf[nt][1] = Ws[nr + g][kk + tig + 4];
            }
#pragma unroll
            for (int mt = 0; mt < 4; mt++)
#pragma unroll
                for (int nt = 0; nt < 4; nt++)
                    mma_tf32(acc[mt][nt], af[mt][0], af[mt][1], af[mt][2], af[mt][3],
                             bf[nt][0], bf[nt][1]);
        }
    }

    // epilogue
#pragma unroll
    for (int mt = 0; mt < 4; mt++) {
#pragma unroll
        for (int half = 0; half < 2; half++) {
            const int row = row0 + wm + mt * 16 + g + half * 8;
#pragma unroll
            for (int nt = 0; nt < 4; nt++) {
                const int col = col0 + wn + nt * 8 + tig * 2;
                float2 v;
                v.x = acc[mt][nt][half * 2 + 0] + bias[col + 0];
                v.y = acc[mt][nt][half * 2 + 1] + bias[col + 1];
                if (SCATTER) {
                    const int bb = row >> 11;
                    const int ss = row & 2047;
                    const int hh = col >> 6;
                    const int dd = col & 63;
                    *(float2*)&C[(((size_t)(bb * NH_ + hh) * S_) + ss) * HD_ + dd] = v;
                } else {
                    *(float2*)&C[(size_t)row * N_ + col] = v;
                }
            }
        }
    }
}

// ---------------------------------------------------------------------------
// Flash attention, tf32 tensor cores.
// Block: 128 threads (4 warps), q-tile = 64 (warp owns 16 q-rows), kv tile = 64.
// Smem: QP[64][68] (Q tf32, later reused per-warp for P), Ks[64][68] (K [kv][d],
// directly the col-major B operand of Q@K^T), Vt[64][68] (V^T [d][kv]).
// ---------------------------------------------------------------------------
#define ATTN_SMEM (3 * 64 * 68 * 4)

__global__ __launch_bounds__(128)
void flash_attn_tc(const float* __restrict__ Q, const float* __restrict__ Kk,
                   const float* __restrict__ V, const float* __restrict__ amask,
                   float* __restrict__ ctx) {
    extern __shared__ uint32_t smu[];
    uint32_t (*QP)[68] = (uint32_t(*)[68])(smu);
    uint32_t (*Ks)[68] = (uint32_t(*)[68])(smu + 64 * 68);
    uint32_t (*Vt)[68] = (uint32_t(*)[68])(smu + 2 * 64 * 68);
    __shared__ float Ms[64];

    const int t    = threadIdx.x;
    const int warp = t >> 5;
    const int lane = t & 31;
    const int g    = lane >> 2;
    const int tig  = lane & 3;
    const int qm   = warp * 16;        // warp's q-row base within tile
    const int b    = blockIdx.z;
    const int h    = blockIdx.y;
    const int q0   = blockIdx.x * 64;

    const float* qb = Q  + ((size_t)(b * NH_ + h) * S_ + q0) * HD_;
    const float* kb = Kk + ((size_t)(b * NH_ + h) * S_) * HD_;
    const float* vb = V  + ((size_t)(b * NH_ + h) * S_) * HD_;
    const float* mb = amask + (size_t)b * S_;

    // Stage Q tile [64 x 64] as tf32
#pragma unroll
    for (int i = 0; i < 8; i++) {
        const int idx = t + i * 128;
        const int r  = idx >> 4;
        const int d4 = (idx & 15) << 2;
        float4 qv = *(const float4*)(qb + (size_t)r * HD_ + d4);
        *(uint4*)&QP[r][d4] = make_uint4(f2tf(qv.x), f2tf(qv.y), f2tf(qv.z), f2tf(qv.w));
    }
    __syncthreads();

    // Q fragments in registers: 8 k-chunks x 4 regs
    uint32_t qf[8][4];
#pragma unroll
    for (int kc = 0; kc < 8; kc++) {
        qf[kc][0] = QP[qm + g][kc * 8 + tig];
        qf[kc][1] = QP[qm + g + 8][kc * 8 + tig];
        qf[kc][2] = QP[qm + g][kc * 8 + tig + 4];
        qf[kc][3] = QP[qm + g + 8][kc * 8 + tig + 4];
    }

    float o[8][4];
#pragma unroll
    for (int nt = 0; nt < 8; nt++)
#pragma unroll
        for (int r = 0; r < 4; r++) o[nt][r] = 0.f;
    float m0 = -1e30f, m1 = -1e30f, l0 = 0.f, l1 = 0.f;

    for (int kv0 = 0; kv0 < S_; kv0 += 64) {
        __syncthreads();  // previous iteration's reads of Ks/Vt done
        // K tile: [kv][d] straight (coalesced), V tile transposed -> Vt[d][kv]
#pragma unroll
        for (int i = 0; i < 8; i++) {
            const int idx = t + i * 128;
            const int r  = idx >> 4;
            const int d4 = (idx & 15) << 2;
            float4 kv4 = *(const float4*)(kb + (size_t)(kv0 + r) * HD_ + d4);
            *(uint4*)&Ks[r][d4] = make_uint4(f2tf(kv4.x), f2tf(kv4.y), f2tf(kv4.z), f2tf(kv4.w));
            const int vr = idx & 63;
            const int c4 = idx >> 6;   // 0..15
            float4 vv = *(const float4*)(vb + (size_t)(kv0 + vr) * HD_ + c4 * 4);
            Vt[c4 * 4 + 0][vr] = f2tf(vv.x);
            Vt[c4 * 4 + 1][vr] = f2tf(vv.y);
            Vt[c4 * 4 + 2][vr] = f2tf(vv.z);
            Vt[c4 * 4 + 3][vr] = f2tf(vv.w);
        }
        if (t < 64) Ms[t] = (1.0f - mb[kv0 + t]) * -10000.0f;
        __syncthreads();

        // S = Q @ K^T  (A = Q frags, B = Ks[kv][d] col-major)
        float s[8][4];
#pragma unroll
        for (int nt = 0; nt < 8; nt++)
#pragma unroll
            for (int r = 0; r < 4; r++) s[nt][r] = 0.f;
#pragma unroll
        for (int kc = 0; kc < 8; kc++) {
#pragma unroll
            for (int nt = 0; nt < 8; nt++) {
                uint32_t b0 = Ks[nt * 8 + g][kc * 8 + tig];
                uint32_t b1 = Ks[nt * 8 + g][kc * 8 + tig + 4];
                mma_tf32(s[nt], qf[kc][0], qf[kc][1], qf[kc][2], qf[kc][3], b0, b1);
            }
        }

        // scale + mask, online softmax (thread owns 2 rows: g, g+8 of warp tile)
        float rmax0 = -1e30f, rmax1 = -1e30f;
#pragma unroll
        for (int nt = 0; nt < 8; nt++) {
            const float madd0 = Ms[nt * 8 + tig * 2];
            const float madd1 = Ms[nt * 8 + tig * 2 + 1];
            s[nt][0] = s[nt][0] * 0.125f + madd0;
            s[nt][1] = s[nt][1] * 0.125f + madd1;
            s[nt][2] = s[nt][2] * 0.125f + madd0;
            s[nt][3] = s[nt][3] * 0.125f + madd1;
            rmax0 = fmaxf(rmax0, fmaxf(s[nt][0], s[nt][1]));
            rmax1 = fmaxf(rmax1, fmaxf(s[nt][2], s[nt][3]));
        }
#pragma unroll
        for (int off = 1; off < 4; off <<= 1) {
            rmax0 = fmaxf(rmax0, __shfl_xor_sync(0xffffffffu, rmax0, off));
            rmax1 = fmaxf(rmax1, __shfl_xor_sync(0xffffffffu, rmax1, off));
        }
        const float m0n = fmaxf(m0, rmax0);
        const float m1n = fmaxf(m1, rmax1);
        const float c0  = __expf(m0 - m0n);
        const float c1  = __expf(m1 - m1n);
        float rs0 = 0.f, rs1 = 0.f;
#pragma unroll
        for (int nt = 0; nt < 8; nt++) {
            s[nt][0] = __expf(s[nt][0] - m0n);
            s[nt][1] = __expf(s[nt][1] - m0n);
            s[nt][2] = __expf(s[nt][2] - m1n);
            s[nt][3] = __expf(s[nt][3] - m1n);
            rs0 += s[nt][0] + s[nt][1];
            rs1 += s[nt][2] + s[nt][3];
        }
#pragma unroll
        for (int off = 1; off < 4; off <<= 1) {
            rs0 += __shfl_xor_sync(0xffffffffu, rs0, off);
            rs1 += __shfl_xor_sync(0xffffffffu, rs1, off);
        }
        l0 = l0 * c0 + rs0;  m0 = m0n;
        l1 = l1 * c1 + rs1;  m1 = m1n;
#pragma unroll
        for (int nt = 0; nt < 8; nt++) {
            o[nt][0] *= c0; o[nt][1] *= c0;
            o[nt][2] *= c1; o[nt][3] *= c1;
        }

        // Store P into warp-private rows of QP (reuse), layout [q][kv]
#pragma unroll
        for (int nt = 0; nt < 8; nt++) {
            *(uint2*)&QP[qm + g][nt * 8 + tig * 2]     = make_uint2(f2tf(s[nt][0]), f2tf(s[nt][1]));
            *(uint2*)&QP[qm + g + 8][nt * 8 + tig * 2] = make_uint2(f2tf(s[nt][2]), f2tf(s[nt][3]));
        }
        __syncwarp();

        // O += P @ V   (A = P frags from QP, B = Vt[d][kv] col-major)
#pragma unroll
        for (int kc = 0; kc < 8; kc++) {
            uint32_t pa0 = QP[qm + g][kc * 8 + tig];
            uint32_t pa1 = QP[qm + g + 8][kc * 8 + tig];
            uint32_t pa2 = QP[qm + g][kc * 8 + tig + 4];
            uint32_t pa3 = QP[qm + g + 8][kc * 8 + tig + 4];
#pragma unroll
            for (int nt = 0; nt < 8; nt++) {
                uint32_t b0 = Vt[nt * 8 + g][kc * 8 + tig];
                uint32_t b1 = Vt[nt * 8 + g][kc * 8 + tig + 4];
                mma_tf32(o[nt], pa0, pa1, pa2, pa3, b0, b1);
            }
        }
        __syncwarp();   // P reads done before next iteration (warp-local)
    }

    // Epilogue: ctx[b][q][h*64+d] = O / l
    const float inv0 = 1.0f / l0;
    const float inv1 = 1.0f / l1;
    const int r0 = q0 + qm + g;
    const int r1 = r0 + 8;
#pragma unroll
    for (int nt = 0; nt < 8; nt++) {
        const int col = h * HD_ + nt * 8 + tig * 2;
        *(float2*)&ctx[((size_t)b * S_ + r0) * H_ + col] =
            make_float2(o[nt][0] * inv0, o[nt][1] * inv0);
        *(float2*)&ctx[((size_t)b * S_ + r1) * H_ + col] =
            make_float2(o[nt][2] * inv1, o[nt][3] * inv1);
    }
}

// ---------------------------------------------------------------------------
extern "C" void kernel_launch(void* const* d_in, const int* in_sizes, int n_in,
                              void* d_out, int out_size) {
    const float* query = (const float*)d_in[0];
    const float* key_  = (const float*)d_in[1];
    const float* value = (const float*)d_in[2];
    const float* amask = (const float*)d_in[3];
    const float* Wq = (const float*)d_in[4];
    const float* bq = (const float*)d_in[5];
    const float* Wk = (const float*)d_in[6];
    const float* bk = (const float*)d_in[7];
    const float* Wv = (const float*)d_in[8];
    const float* bv = (const float*)d_in[9];
    const float* Wo = (const float*)d_in[10];
    const float* bo = (const float*)d_in[11];
    float* out = (float*)d_out;

    float *qp, *kp, *vp, *cp;
    cudaGetSymbolAddress((void**)&qp, g_q);
    cudaGetSymbolAddress((void**)&kp, g_k);
    cudaGetSymbolAddress((void**)&vp, g_v);
    cudaGetSymbolAddress((void**)&cp, g_ctx);

    cudaFuncSetAttribute(flash_attn_tc,
                         cudaFuncAttributeMaxDynamicSharedMemorySize, ATTN_SMEM);

    dim3 gblk(256);
    dim3 ggrid(N_ / 128, M_ / 128);   // (8, 64)

    gemm_tc<1><<<ggrid, gblk>>>(query, Wq, bq, qp);
    gemm_tc<1><<<ggrid, gblk>>>(key_,  Wk, bk, kp);
    gemm_tc<1><<<ggrid, gblk>>>(value, Wv, bv, vp);

    flash_attn_tc<<<dim3(S_ / 64, NH_, B_), 128, ATTN_SMEM>>>(qp, kp, vp, amask, cp);

    gemm_tc<0><<<ggrid, gblk>>>(cp, Wo, bo, out);
}

// round 3
// speedup vs baseline: 3.0583x; 1.2694x over previous
#include <cuda_runtime.h>
#include <cuda_bf16.h>
#include <math.h>
#include <stdint.h>

#define B_  4
#define S_  2048
#define H_  1024
#define NH_ 16
#define HD_ 64
#define M_  (B_ * S_)
#define K_  1024
#define N_  1024

#define LOG2E 1.4426950408889634f
#define SCL   0.18033688011112042f   // 0.125 * log2(e)

// Scratch (device globals; allocation-free per harness rules)
__device__ uint32_t g_xq[M_ * K_];   // tf32 inputs
__device__ uint32_t g_xk[M_ * K_];
__device__ uint32_t g_xv[M_ * K_];
__device__ uint32_t g_wq[N_ * K_];   // tf32 weights
__device__ uint32_t g_wk[N_ * K_];
__device__ uint32_t g_wv[N_ * K_];
__device__ uint32_t g_wo[N_ * K_];
__device__ uint32_t g_q[B_ * S_ * H_];    // tf32 [B,NH,S,HD]
__device__ uint32_t g_k[B_ * S_ * H_];    // tf32 [B,NH,S,HD]
__device__ uint32_t g_v[B_ * S_ * H_];    // tf32 [B,NH,HD,S]  (transposed!)
__device__ uint32_t g_ctx[B_ * S_ * H_];  // tf32 [B,S,H]

// ---------------------------------------------------------------------------
__device__ __forceinline__ uint32_t f2tf(float f) {
    uint32_t u;
    asm("cvt.rna.tf32.f32 %0, %1;" : "=r"(u) : "f"(f));
    return u;
}
__device__ __forceinline__ float ex2(float x) {
    float y;
    asm("ex2.approx.ftz.f32 %0, %1;" : "=f"(y) : "f"(x));
    return y;
}
__device__ __forceinline__ void mma_tf32(float c[4],
                                         uint32_t a0, uint32_t a1,
                                         uint32_t a2, uint32_t a3,
                                         uint32_t b0, uint32_t b1) {
    asm volatile(
        "mma.sync.aligned.m16n8k8.row.col.f32.tf32.tf32.f32 "
        "{%0,%1,%2,%3},{%4,%5,%6,%7},{%8,%9},{%0,%1,%2,%3};"
        : "+f"(c[0]), "+f"(c[1]), "+f"(c[2]), "+f"(c[3])
        : "r"(a0), "r"(a1), "r"(a2), "r"(a3), "r"(b0), "r"(b1));
}
__device__ __forceinline__ void cp16(uint32_t smem, const void* g) {
    asm volatile("cp.async.cg.shared.global [%0], [%1], 16;" :: "r"(smem), "l"(g));
}
#define CP_COMMIT() asm volatile("cp.async.commit_group;")
#define CP_WAIT(N)  asm volatile("cp.async.wait_group %0;" :: "n"(N))

// ---------------------------------------------------------------------------
// Prepass: fp32 -> tf32 (rna), elementwise
// ---------------------------------------------------------------------------
__global__ void cvt_tf32_kernel(const float4* __restrict__ src,
                                uint4* __restrict__ dst, int n4) {
    int i = blockIdx.x * blockDim.x + threadIdx.x;
    const int stride = gridDim.x * blockDim.x;
    for (; i < n4; i += stride) {
        float4 v = src[i];
        dst[i] = make_uint4(f2tf(v.x), f2tf(v.y), f2tf(v.z), f2tf(v.w));
    }
}

// ---------------------------------------------------------------------------
// GEMM: C = A @ W^T + bias.  A:[M,K] tf32, W:[N,K] tf32.
// 128x128x16 tiles, 256 threads, 3-stage cp.async pipeline.
// SCATTER: 0 = plain fp32 [M,N]; 1 = tf32 [B,NH,S,HD]; 2 = tf32 [B,NH,HD,S].
// ---------------------------------------------------------------------------
#define GSM_STAGE 2560              // 128*20 u32 per stage per matrix
#define GEMM_SMEM (2 * 3 * GSM_STAGE * 4)

template <int SCATTER>
__global__ __launch_bounds__(256, 2)
void gemm_tc2(const uint32_t* __restrict__ A, const uint32_t* __restrict__ W,
              const float* __restrict__ bias, void* __restrict__ Cv) {
    extern __shared__ uint32_t smu[];
    uint32_t* smA = smu;                  // [3][128][20]
    uint32_t* smW = smu + 3 * GSM_STAGE;  // [3][128][20]

    const int t    = threadIdx.x;
    const int warp = t >> 5;
    const int lane = t & 31;
    const int g    = lane >> 2;
    const int tig  = lane & 3;
    const int wm   = (warp & 1) * 64;
    const int wn   = (warp >> 1) * 32;
    const int row0 = blockIdx.y * 128;
    const int col0 = blockIdx.x * 128;

    // staging: 512 16B-chunks per matrix per stage -> 2 per thread
    const int r0c = t >> 2,            c0c = (t & 3) * 4;
    const int r1c = (t + 256) >> 2,    c1c = ((t + 256) & 3) * 4;
    const uint32_t* Ap = A + (size_t)row0 * K_;
    const uint32_t* Wp = W + (size_t)col0 * K_;

    uint32_t sA0 = (uint32_t)__cvta_generic_to_shared(smA) + (r0c * 20 + c0c) * 4;
    uint32_t sA1 = (uint32_t)__cvta_generic_to_shared(smA) + (r1c * 20 + c1c) * 4;
    uint32_t sW0 = (uint32_t)__cvta_generic_to_shared(smW) + (r0c * 20 + c0c) * 4;
    uint32_t sW1 = (uint32_t)__cvta_generic_to_shared(smW) + (r1c * 20 + c1c) * 4;

#define G_ISSUE(tt) do {                                                       \
        const int st_ = (tt) % 3;                                              \
        const int k0_ = (tt) * 16;                                             \
        cp16(sA0 + st_ * GSM_STAGE * 4, Ap + (size_t)r0c * K_ + k0_ + c0c);    \
        cp16(sA1 + st_ * GSM_STAGE * 4, Ap + (size_t)r1c * K_ + k0_ + c1c);    \
        cp16(sW0 + st_ * GSM_STAGE * 4, Wp + (size_t)r0c * K_ + k0_ + c0c);    \
        cp16(sW1 + st_ * GSM_STAGE * 4, Wp + (size_t)r1c * K_ + k0_ + c1c);    \
    } while (0)

    float acc[4][4][4];
#pragma unroll
    for (int i = 0; i < 4; i++)
#pragma unroll
        for (int j = 0; j < 4; j++)
#pragma unroll
            for (int r = 0; r < 4; r++) acc[i][j][r] = 0.f;

    G_ISSUE(0); CP_COMMIT();
    G_ISSUE(1); CP_COMMIT();

    const int NT = K_ / 16;   // 64
    for (int tt = 0; tt < NT; tt++) {
        if (tt + 2 < NT) G_ISSUE(tt + 2);
        CP_COMMIT();
        CP_WAIT(2);
        __syncthreads();

        const uint32_t* Ab = smA + (tt % 3) * GSM_STAGE;
        const uint32_t* Wb = smW + (tt % 3) * GSM_STAGE;
#pragma unroll
        for (int kk = 0; kk < 16; kk += 8) {
            uint32_t af[4][4], bf[4][2];
#pragma unroll
            for (int mt = 0; mt < 4; mt++) {
                const int mr = wm + mt * 16;
                af[mt][0] = Ab[(mr + g) * 20 + kk + tig];
                af[mt][1] = Ab[(mr + g + 8) * 20 + kk + tig];
                af[mt][2] = Ab[(mr + g) * 20 + kk + tig + 4];
                af[mt][3] = Ab[(mr + g + 8) * 20 + kk + tig + 4];
            }
#pragma unroll
            for (int nt = 0; nt < 4; nt++) {
                const int nr = wn + nt * 8;
                bf[nt][0] = Wb[(nr + g) * 20 + kk + tig];
                bf[nt][1] = Wb[(nr + g) * 20 + kk + tig + 4];
            }
#pragma unroll
            for (int mt = 0; mt < 4; mt++)
#pragma unroll
                for (int nt = 0; nt < 4; nt++)
                    mma_tf32(acc[mt][nt], af[mt][0], af[mt][1], af[mt][2], af[mt][3],
                             bf[nt][0], bf[nt][1]);
        }
        __syncthreads();
    }
#undef G_ISSUE

    // epilogue
#pragma unroll
    for (int mt = 0; mt < 4; mt++) {
#pragma unroll
        for (int half = 0; half < 2; half++) {
            const int row = row0 + wm + mt * 16 + g + half * 8;
#pragma unroll
            for (int nt = 0; nt < 4; nt++) {
                const int col = col0 + wn + nt * 8 + tig * 2;
                const float vx = acc[mt][nt][half * 2 + 0] + bias[col + 0];
                const float vy = acc[mt][nt][half * 2 + 1] + bias[col + 1];
                const int bb = row >> 11, ss = row & 2047;
                const int hh = col >> 6,  dd = col & 63;
                if (SCATTER == 0) {
                    *(float2*)&((float*)Cv)[(size_t)row * N_ + col] = make_float2(vx, vy);
                } else if (SCATTER == 1) {
                    *(uint2*)&((uint32_t*)Cv)[(((size_t)(bb * NH_ + hh) * S_) + ss) * HD_ + dd] =
                        make_uint2(f2tf(vx), f2tf(vy));
                } else {
                    uint32_t* C = (uint32_t*)Cv;
                    const size_t base = ((size_t)(bb * NH_ + hh) * HD_ + dd) * S_ + ss;
                    C[base]      = f2tf(vx);
                    C[base + S_] = f2tf(vy);
                }
            }
        }
    }
}

// ---------------------------------------------------------------------------
// Flash attention (tf32 MMA, base-2 online softmax, cp.async double buffering).
// Block: 128 threads (4 warps), q-tile 64 (warp = 16 rows), kv-tile 64.
// Q/K tf32 [B,NH,S,HD]; V tf32 [B,NH,HD,S] (pre-transposed by its GEMM).
// smem u32 layout: QP[64][68] | Ks[2][64][68] | Vt[2][64][68] | Msk[2][64]
// ---------------------------------------------------------------------------
#define QP_OFF   0
#define KS_OFF   4352
#define VT_OFF   13056
#define MSK_OFF  21760
#define ATTN_SMEM ((21760 + 128) * 4)

__global__ __launch_bounds__(128)
void flash_attn_tc2(const uint32_t* __restrict__ Q, const uint32_t* __restrict__ Kk,
                    const uint32_t* __restrict__ V, const float* __restrict__ amask,
                    uint32_t* __restrict__ ctx) {
    extern __shared__ uint32_t smu[];
    uint32_t* QP  = smu + QP_OFF;    // [64][68]
    uint32_t* Ks  = smu + KS_OFF;    // [2][64][68]
    uint32_t* Vt  = smu + VT_OFF;    // [2][64][68]
    float*    Msk = (float*)(smu + MSK_OFF);  // [2][64]
    const uint32_t smbase = (uint32_t)__cvta_generic_to_shared(smu);

    const int t    = threadIdx.x;
    const int warp = t >> 5;
    const int lane = t & 31;
    const int g    = lane >> 2;
    const int tig  = lane & 3;
    const int qm   = warp * 16;
    const int b    = blockIdx.z;
    const int h    = blockIdx.y;
    const int q0   = blockIdx.x * 64;

    const uint32_t* qb = Q  + ((size_t)(b * NH_ + h) * S_ + q0) * HD_;
    const uint32_t* kb = Kk + ((size_t)(b * NH_ + h) * S_) * HD_;
    const uint32_t* vb = V  + ((size_t)(b * NH_ + h) * HD_) * S_;
    const float*    mb = amask + (size_t)b * S_;

    // chunk mapping for 64x64 tiles: idx = t + i*128, i=0..7
    const int cr = t >> 4;            // row step base
    const int cc = (t & 15) << 2;     // col (u32)

#define F_ISSUE(tt) do {                                                          \
        const int bf_ = (tt) & 1;                                                 \
        const int kv_ = (tt) * 64;                                                \
        _Pragma("unroll")                                                         \
        for (int i = 0; i < 8; i++) {                                             \
            const int r_ = cr + i * 8;                                            \
            cp16(smbase + (KS_OFF + bf_ * 4352 + r_ * 68 + cc) * 4,               \
                 kb + (size_t)(kv_ + r_) * HD_ + cc);                             \
            cp16(smbase + (VT_OFF + bf_ * 4352 + r_ * 68 + cc) * 4,               \
                 vb + (size_t)r_ * S_ + kv_ + cc);                                \
        }                                                                         \
        if (t < 16)                                                               \
            cp16(smbase + (MSK_OFF + bf_ * 64 + t * 4) * 4, mb + kv_ + t * 4);    \
    } while (0)

    // prologue: Q tile + tile 0
#pragma unroll
    for (int i = 0; i < 8; i++) {
        const int r_ = cr + i * 8;
        cp16(smbase + (QP_OFF + r_ * 68 + cc) * 4, qb + (size_t)r_ * HD_ + cc);
    }
    F_ISSUE(0);
    CP_COMMIT();
    CP_WAIT(0);
    __syncthreads();

    // Q fragments to registers
    uint32_t qf[8][4];
#pragma unroll
    for (int kc = 0; kc < 8; kc++) {
        qf[kc][0] = QP[(qm + g) * 68 + kc * 8 + tig];
        qf[kc][1] = QP[(qm + g + 8) * 68 + kc * 8 + tig];
        qf[kc][2] = QP[(qm + g) * 68 + kc * 8 + tig + 4];
        qf[kc][3] = QP[(qm + g + 8) * 68 + kc * 8 + tig + 4];
    }

    float o[8][4];
#pragma unroll
    for (int nt = 0; nt < 8; nt++)
#pragma unroll
        for (int r = 0; r < 4; r++) o[nt][r] = 0.f;
    float m0 = -1e30f, m1 = -1e30f, l0 = 0.f, l1 = 0.f;

    const int NT = S_ / 64;   // 32
    for (int tt = 0; tt < NT; tt++) {
        if (tt + 1 < NT) F_ISSUE(tt + 1);
        CP_COMMIT();
        CP_WAIT(1);
        __syncthreads();

        const uint32_t* Kb = Ks + (tt & 1) * 4352;
        const uint32_t* Vb = Vt + (tt & 1) * 4352;
        const float*    Mb = Msk + (tt & 1) * 64;

        // S = Q @ K^T
        float s[8][4];
#pragma unroll
        for (int nt = 0; nt < 8; nt++)
#pragma unroll
            for (int r = 0; r < 4; r++) s[nt][r] = 0.f;
#pragma unroll
        for (int kc = 0; kc < 8; kc++) {
#pragma unroll
            for (int nt = 0; nt < 8; nt++) {
                uint32_t b0 = Kb[(nt * 8 + g) * 68 + kc * 8 + tig];
                uint32_t b1 = Kb[(nt * 8 + g) * 68 + kc * 8 + tig + 4];
                mma_tf32(s[nt], qf[kc][0], qf[kc][1], qf[kc][2], qf[kc][3], b0, b1);
            }
        }

        // base-2 online softmax; thread owns rows g and g+8 of warp tile
        float rmax0 = -1e30f, rmax1 = -1e30f;
#pragma unroll
        for (int nt = 0; nt < 8; nt++) {
            const float2 mm = *(const float2*)&Mb[nt * 8 + tig * 2];
            const float madd0 = (1.0f - mm.x) * (-10000.0f * LOG2E);
            const float madd1 = (1.0f - mm.y) * (-10000.0f * LOG2E);
            s[nt][0] = fmaf(s[nt][0], SCL, madd0);
            s[nt][1] = fmaf(s[nt][1], SCL, madd1);
            s[nt][2] = fmaf(s[nt][2], SCL, madd0);
            s[nt][3] = fmaf(s[nt][3], SCL, madd1);
            rmax0 = fmaxf(rmax0, fmaxf(s[nt][0], s[nt][1]));
            rmax1 = fmaxf(rmax1, fmaxf(s[nt][2], s[nt][3]));
        }
#pragma unroll
        for (int off = 1; off < 4; off <<= 1) {
            rmax0 = fmaxf(rmax0, __shfl_xor_sync(0xffffffffu, rmax0, off));
            rmax1 = fmaxf(rmax1, __shfl_xor_sync(0xffffffffu, rmax1, off));
        }
        const float m0n = fmaxf(m0, rmax0);
        const float m1n = fmaxf(m1, rmax1);
        const float c0  = ex2(m0 - m0n);
        const float c1  = ex2(m1 - m1n);
        float rs0 = 0.f, rs1 = 0.f;
#pragma unroll
        for (int nt = 0; nt < 8; nt++) {
            s[nt][0] = ex2(s[nt][0] - m0n);
            s[nt][1] = ex2(s[nt][1] - m0n);
            s[nt][2] = ex2(s[nt][2] - m1n);
            s[nt][3] = ex2(s[nt][3] - m1n);
            rs0 += s[nt][0] + s[nt][1];
            rs1 += s[nt][2] + s[nt][3];
        }
#pragma unroll
        for (int off = 1; off < 4; off <<= 1) {
            rs0 += __shfl_xor_sync(0xffffffffu, rs0, off);
            rs1 += __shfl_xor_sync(0xffffffffu, rs1, off);
        }
        l0 = l0 * c0 + rs0;  m0 = m0n;
        l1 = l1 * c1 + rs1;  m1 = m1n;
#pragma unroll
        for (int nt = 0; nt < 8; nt++) {
            o[nt][0] *= c0; o[nt][1] *= c0;
            o[nt][2] *= c1; o[nt][3] *= c1;
        }

        // P -> warp-private rows of QP (tf32)
#pragma unroll
        for (int nt = 0; nt < 8; nt++) {
            *(uint2*)&QP[(qm + g) * 68 + nt * 8 + tig * 2] =
                make_uint2(f2tf(s[nt][0]), f2tf(s[nt][1]));
            *(uint2*)&QP[(qm + g + 8) * 68 + nt * 8 + tig * 2] =
                make_uint2(f2tf(s[nt][2]), f2tf(s[nt][3]));
        }
        __syncwarp();

        // O += P @ V
#pragma unroll
        for (int kc = 0; kc < 8; kc++) {
            uint32_t pa0 = QP[(qm + g) * 68 + kc * 8 + tig];
            uint32_t pa1 = QP[(qm + g + 8) * 68 + kc * 8 + tig];
            uint32_t pa2 = QP[(qm + g) * 68 + kc * 8 + tig + 4];
            uint32_t pa3 = QP[(qm + g + 8) * 68 + kc * 8 + tig + 4];
#pragma unroll
            for (int nt = 0; nt < 8; nt++) {
                uint32_t b0 = Vb[(nt * 8 + g) * 68 + kc * 8 + tig];
                uint32_t b1 = Vb[(nt * 8 + g) * 68 + kc * 8 + tig + 4];
                mma_tf32(o[nt], pa0, pa1, pa2, pa3, b0, b1);
            }
        }
        __syncwarp();
        __syncthreads();   // all reads of this buffer done before reuse
    }
#undef F_ISSUE

    // epilogue: ctx[b][q][h*64+d] = O / l   (stored tf32 for the final GEMM)
    const float inv0 = 1.0f / l0;
    const float inv1 = 1.0f / l1;
    const int r0 = q0 + qm + g;
    const int r1 = r0 + 8;
#pragma unroll
    for (int nt = 0; nt < 8; nt++) {
        const int col = h * HD_ + nt * 8 + tig * 2;
        *(uint2*)&ctx[((size_t)b * S_ + r0) * H_ + col] =
            make_uint2(f2tf(o[nt][0] * inv0), f2tf(o[nt][1] * inv0));
        *(uint2*)&ctx[((size_t)b * S_ + r1) * H_ + col] =
            make_uint2(f2tf(o[nt][2] * inv1), f2tf(o[nt][3] * inv1));
    }
}

// ---------------------------------------------------------------------------
extern "C" void kernel_launch(void* const* d_in, const int* in_sizes, int n_in,
                              void* d_out, int out_size) {
    const float* query = (const float*)d_in[0];
    const float* key_  = (const float*)d_in[1];
    const float* value = (const float*)d_in[2];
    const float* amask = (const float*)d_in[3];
    const float* Wq = (const float*)d_in[4];
    const float* bq = (const float*)d_in[5];
    const float* Wk = (const float*)d_in[6];
    const float* bk = (const float*)d_in[7];
    const float* Wv = (const float*)d_in[8];
    const float* bv = (const float*)d_in[9];
    const float* Wo = (const float*)d_in[10];
    const float* bo = (const float*)d_in[11];
    float* out = (float*)d_out;

    uint32_t *xq, *xk, *xv, *wq, *wk, *wv, *wo, *qp, *kp, *vp, *cp;
    cudaGetSymbolAddress((void**)&xq, g_xq);
    cudaGetSymbolAddress((void**)&xk, g_xk);
    cudaGetSymbolAddress((void**)&xv, g_xv);
    cudaGetSymbolAddress((void**)&wq, g_wq);
    cudaGetSymbolAddress((void**)&wk, g_wk);
    cudaGetSymbolAddress((void**)&wv, g_wv);
    cudaGetSymbolAddress((void**)&wo, g_wo);
    cudaGetSymbolAddress((void**)&qp, g_q);
    cudaGetSymbolAddress((void**)&kp, g_k);
    cudaGetSymbolAddress((void**)&vp, g_v);
    cudaGetSymbolAddress((void**)&cp, g_ctx);

    cudaFuncSetAttribute(gemm_tc2<0>, cudaFuncAttributeMaxDynamicSharedMemorySize, GEMM_SMEM);
    cudaFuncSetAttribute(gemm_tc2<1>, cudaFuncAttributeMaxDynamicSharedMemorySize, GEMM_SMEM);
    cudaFuncSetAttribute(gemm_tc2<2>, cudaFuncAttributeMaxDynamicSharedMemorySize, GEMM_SMEM);
    cudaFuncSetAttribute(flash_attn_tc2, cudaFuncAttributeMaxDynamicSharedMemorySize, ATTN_SMEM);

    // prepass conversions
    const int n4_in = M_ * K_ / 4;   // 2097152
    const int n4_w  = N_ * K_ / 4;   // 262144
    cvt_tf32_kernel<<<1024, 256>>>((const float4*)query, (uint4*)xq, n4_in);
    cvt_tf32_kernel<<<1024, 256>>>((const float4*)key_,  (uint4*)xk, n4_in);
    cvt_tf32_kernel<<<1024, 256>>>((const float4*)value, (uint4*)xv, n4_in);
    cvt_tf32_kernel<<<512, 256>>>((const float4*)Wq, (uint4*)wq, n4_w);
    cvt_tf32_kernel<<<512, 256>>>((const float4*)Wk, (uint4*)wk, n4_w);
    cvt_tf32_kernel<<<512, 256>>>((const float4*)Wv, (uint4*)wv, n4_w);
    cvt_tf32_kernel<<<512, 256>>>((const float4*)Wo, (uint4*)wo, n4_w);

    dim3 gblk(256);
    dim3 ggrid(N_ / 128, M_ / 128);   // (8, 64)
    gemm_tc2<1><<<ggrid, gblk, GEMM_SMEM>>>(xq, wq, bq, qp);
    gemm_tc2<1><<<ggrid, gblk, GEMM_SMEM>>>(xk, wk, bk, kp);
    gemm_tc2<2><<<ggrid, gblk, GEMM_SMEM>>>(xv, wv, bv, vp);

    flash_attn_tc2<<<dim3(S_ / 64, NH_, B_), 128, ATTN_SMEM>>>(qp, kp, vp, amask, cp);

    gemm_tc2<0><<<ggrid, gblk, GEMM_SMEM>>>(cp, wo, bo, out);
}

// round 5
// speedup vs baseline: 3.2939x; 1.0771x over previous
#include <cuda_runtime.h>
#include <cuda_bf16.h>
#include <math.h>
#include <stdint.h>

#define B_  4
#define S_  2048
#define H_  1024
#define NH_ 16
#define HD_ 64
#define M_  (B_ * S_)
#define K_  1024
#define N_  1024

#define LOG2E 1.4426950408889634f
#define SCL   0.18033688011112042f   // 0.125 * log2(e)

// Scratch (device globals; allocation-free per harness rules)
__device__ uint32_t g_xq[M_ * K_];
__device__ uint32_t g_xk[M_ * K_];
__device__ uint32_t g_xv[M_ * K_];
__device__ uint32_t g_wq[N_ * K_];
__device__ uint32_t g_wk[N_ * K_];
__device__ uint32_t g_wv[N_ * K_];
__device__ uint32_t g_wo[N_ * K_];
__device__ uint32_t g_q[B_ * S_ * H_];    // tf32 [B,NH,S,HD]
__device__ uint32_t g_k[B_ * S_ * H_];    // tf32 [B,NH,S,HD]
__device__ uint32_t g_v[B_ * S_ * H_];    // tf32 [B,NH,HD,S]  (transposed)
__device__ uint32_t g_ctx[B_ * S_ * H_];  // tf32 [B,S,H]

// ---------------------------------------------------------------------------
__device__ __forceinline__ uint32_t f2tf(float f) {
    uint32_t u;
    asm("cvt.rna.tf32.f32 %0, %1;" : "=r"(u) : "f"(f));
    return u;
}
__device__ __forceinline__ float ex2(float x) {
    float y;
    asm("ex2.approx.ftz.f32 %0, %1;" : "=f"(y) : "f"(x));
    return y;
}
__device__ __forceinline__ void mma_tf32(float c[4],
                                         uint32_t a0, uint32_t a1,
                                         uint32_t a2, uint32_t a3,
                                         uint32_t b0, uint32_t b1) {
    asm volatile(
        "mma.sync.aligned.m16n8k8.row.col.f32.tf32.tf32.f32 "
        "{%0,%1,%2,%3},{%4,%5,%6,%7},{%8,%9},{%0,%1,%2,%3};"
        : "+f"(c[0]), "+f"(c[1]), "+f"(c[2]), "+f"(c[3])
        : "r"(a0), "r"(a1), "r"(a2), "r"(a3), "r"(b0), "r"(b1));
}
__device__ __forceinline__ void cp16(uint32_t smem, const void* g) {
    asm volatile("cp.async.cg.shared.global [%0], [%1], 16;" :: "r"(smem), "l"(g));
}
#define CP_COMMIT() asm volatile("cp.async.commit_group;")
#define CP_WAIT(N)  asm volatile("cp.async.wait_group %0;" :: "n"(N))

// ---------------------------------------------------------------------------
// Merged prepass: fp32 -> tf32 (rna), 7 jobs via blockIdx.z
// ---------------------------------------------------------------------------
struct CvtBatch {
    const float4* s[7];
    uint4*        d[7];
    int           n4[7];
};
__global__ void cvt7_kernel(CvtBatch cb) {
    const int z = blockIdx.z;
    const float4* __restrict__ src = cb.s[z];
    uint4* __restrict__ dst = cb.d[z];
    const int n4 = cb.n4[z];
    int i = blockIdx.x * blockDim.x + threadIdx.x;
    const int stride = gridDim.x * blockDim.x;
    for (; i < n4; i += stride) {
        float4 v = src[i];
        dst[i] = make_uint4(f2tf(v.x), f2tf(v.y), f2tf(v.z), f2tf(v.w));
    }
}

// ---------------------------------------------------------------------------
// GEMM: C = A @ W^T + bias (tf32 in). 128x128x16 tiles, 256 thr, 3-stage
// cp.async, ONE barrier per k-iter.
// ---------------------------------------------------------------------------
struct GemmBatch {
    const uint32_t* A[3];
    const uint32_t* W[3];
    const float*    bias[3];
    uint32_t*       C[3];
};
#define GSM_STAGE 2560              // 128*20 u32 per stage per matrix
#define GEMM_SMEM (2 * 3 * GSM_STAGE * 4)

template <int QKV>
__global__ __launch_bounds__(256, 2)
void gemm3(GemmBatch gb) {
    extern __shared__ uint32_t smu[];
    uint32_t* smA = smu;
    uint32_t* smW = smu + 3 * GSM_STAGE;

    const int z = QKV ? blockIdx.z : 0;
    const uint32_t* __restrict__ A = gb.A[z];
    const uint32_t* __restrict__ W = gb.W[z];
    const float*    __restrict__ bias = gb.bias[z];
    uint32_t* __restrict__ C = gb.C[z];

    const int t    = threadIdx.x;
    const int warp = t >> 5;
    const int lane = t & 31;
    const int g    = lane >> 2;
    const int tig  = lane & 3;
    const int wm   = (warp & 1) * 64;
    const int wn   = (warp >> 1) * 32;
    const int row0 = blockIdx.y * 128;
    const int col0 = blockIdx.x * 128;

    // staging: 128 rows x 16 k-cols = 512 chunks -> 2/thread
    const int r0c = t >> 2,         c0c = (t & 3) * 4;
    const int r1c = (t + 256) >> 2, c1c = ((t + 256) & 3) * 4;
    const uint32_t* Ap = A + (size_t)row0 * K_;
    const uint32_t* Wp = W + (size_t)col0 * K_;

    const uint32_t sA0 = (uint32_t)__cvta_generic_to_shared(smA) + (r0c * 20 + c0c) * 4;
    const uint32_t sA1 = (uint32_t)__cvta_generic_to_shared(smA) + (r1c * 20 + c1c) * 4;
    const uint32_t sW0 = (uint32_t)__cvta_generic_to_shared(smW) + (r0c * 20 + c0c) * 4;
    const uint32_t sW1 = (uint32_t)__cvta_generic_to_shared(smW) + (r1c * 20 + c1c) * 4;

#define G_ISSUE(tt) do {                                                       \
        const int st_ = (tt) % 3;                                              \
        const int k0_ = (tt) * 16;                                             \
        cp16(sA0 + st_ * GSM_STAGE * 4, Ap + (size_t)r0c * K_ + k0_ + c0c);    \
        cp16(sA1 + st_ * GSM_STAGE * 4, Ap + (size_t)r1c * K_ + k0_ + c1c);    \
        cp16(sW0 + st_ * GSM_STAGE * 4, Wp + (size_t)r0c * K_ + k0_ + c0c);    \
        cp16(sW1 + st_ * GSM_STAGE * 4, Wp + (size_t)r1c * K_ + k0_ + c1c);    \
    } while (0)

    float acc[4][4][4];
#pragma unroll
    for (int i = 0; i < 4; i++)
#pragma unroll
        for (int j = 0; j < 4; j++)
#pragma unroll
            for (int r = 0; r < 4; r++) acc[i][j][r] = 0.f;

    G_ISSUE(0); CP_COMMIT();
    G_ISSUE(1); CP_COMMIT();

    const int NT = K_ / 16;   // 64
    for (int tt = 0; tt < NT; tt++) {
        CP_WAIT(1);            // stage tt resident
        __syncthreads();       // visible block-wide; stage tt-1 reads done
        if (tt + 2 < NT) G_ISSUE(tt + 2);
        CP_COMMIT();

        const uint32_t* Ab = smA + (tt % 3) * GSM_STAGE;
        const uint32_t* Wb = smW + (tt % 3) * GSM_STAGE;
#pragma unroll
        for (int kk = 0; kk < 16; kk += 8) {
            uint32_t af[4][4], bf[4][2];
#pragma unroll
            for (int mt = 0; mt < 4; mt++) {
                const int mr = wm + mt * 16;
                af[mt][0] = Ab[(mr + g) * 20 + kk + tig];
                af[mt][1] = Ab[(mr + g + 8) * 20 + kk + tig];
                af[mt][2] = Ab[(mr + g) * 20 + kk + tig + 4];
                af[mt][3] = Ab[(mr + g + 8) * 20 + kk + tig + 4];
            }
#pragma unroll
            for (int nt = 0; nt < 4; nt++) {
                const int nr = wn + nt * 8;
                bf[nt][0] = Wb[(nr + g) * 20 + kk + tig];
                bf[nt][1] = Wb[(nr + g) * 20 + kk + tig + 4];
            }
#pragma unroll
            for (int mt = 0; mt < 4; mt++)
#pragma unroll
                for (int nt = 0; nt < 4; nt++)
                    mma_tf32(acc[mt][nt], af[mt][0], af[mt][1], af[mt][2], af[mt][3],
                             bf[nt][0], bf[nt][1]);
        }
    }
#undef G_ISSUE

#pragma unroll
    for (int mt = 0; mt < 4; mt++) {
#pragma unroll
        for (int half = 0; half < 2; half++) {
            const int row = row0 + wm + mt * 16 + g + half * 8;
#pragma unroll
            for (int nt = 0; nt < 4; nt++) {
                const int col = col0 + wn + nt * 8 + tig * 2;
                const float vx = acc[mt][nt][half * 2 + 0] + bias[col + 0];
                const float vy = acc[mt][nt][half * 2 + 1] + bias[col + 1];
                const int bb = row >> 11, ss = row & 2047;
                const int hh = col >> 6,  dd = col & 63;
                if (!QKV) {
                    *(float2*)&((float*)C)[(size_t)row * N_ + col] = make_float2(vx, vy);
                } else if (z < 2) {
                    *(uint2*)&C[(((size_t)(bb * NH_ + hh) * S_) + ss) * HD_ + dd] =
                        make_uint2(f2tf(vx), f2tf(vy));
                } else {
                    const size_t base = ((size_t)(bb * NH_ + hh) * HD_ + dd) * S_ + ss;
                    C[base]      = f2tf(vx);
                    C[base + S_] = f2tf(vy);
                }
            }
        }
    }
}

// ---------------------------------------------------------------------------
// Flash attention: q-tile 128, 256 threads (8 warps, warp = 16 q-rows),
// kv-tile 64, triple-buffered K/V via cp.async, ONE barrier per kv-iter.
// Q/K tf32 [B,NH,S,HD]; V tf32 [B,NH,HD,S].
// smem u32: QP[128][68] | Ks[3][64][68] | Vt[3][64][68] | Msk[3][64]
// ---------------------------------------------------------------------------
#define QP_OFF   0
#define KS_OFF   8704
#define VT_OFF   21760
#define MSK_OFF  34816
#define ATTN_SMEM ((34816 + 192) * 4)   // 140,032 B

__global__ __launch_bounds__(256)
void flash_attn_tc3(const uint32_t* __restrict__ Q, const uint32_t* __restrict__ Kk,
                    const uint32_t* __restrict__ V, const float* __restrict__ amask,
                    uint32_t* __restrict__ ctx) {
    extern __shared__ uint32_t smu[];
    uint32_t* QP = smu + QP_OFF;     // [128][68]
    const uint32_t smbase = (uint32_t)__cvta_generic_to_shared(smu);

    const int t    = threadIdx.x;
    const int warp = t >> 5;
    const int lane = t & 31;
    const int g    = lane >> 2;
    const int tig  = lane & 3;
    const int qm   = warp * 16;        // warp q-row base (0..112)
    const int b    = blockIdx.z;
    const int h    = blockIdx.y;
    const int q0   = blockIdx.x * 128;

    const uint32_t* qb = Q  + ((size_t)(b * NH_ + h) * S_ + q0) * HD_;
    const uint32_t* kb = Kk + ((size_t)(b * NH_ + h) * S_) * HD_;
    const uint32_t* vb = V  + ((size_t)(b * NH_ + h) * HD_) * S_;
    const float*    mb = amask + (size_t)b * S_;

    // K/V tile: 64 rows x 64 u32 = 1024 16B-chunks -> 4 per thread.
    // chunk idx = t + i*256: row = idx>>4 (0..63), col = (idx&15)*4 (0..60)
#define F_ISSUE(tt) do {                                                          \
        const int st_ = (tt) % 3;                                                 \
        const int kv_ = (tt) * 64;                                                \
        _Pragma("unroll")                                                         \
        for (int i = 0; i < 4; i++) {                                             \
            const int idx_ = t + i * 256;                                         \
            const int r_ = idx_ >> 4;                                             \
            const int c_ = (idx_ & 15) << 2;                                      \
            cp16(smbase + (KS_OFF + st_ * 4352 + r_ * 68 + c_) * 4,               \
                 kb + (size_t)(kv_ + r_) * HD_ + c_);                             \
            cp16(smbase + (VT_OFF + st_ * 4352 + r_ * 68 + c_) * 4,               \
                 vb + (size_t)r_ * S_ + kv_ + c_);                                \
        }                                                                         \
        if (t < 16)                                                               \
            cp16(smbase + (MSK_OFF + st_ * 64 + t * 4) * 4, mb + kv_ + t * 4);    \
    } while (0)

    // prologue: Q tile 128 rows x 64 u32 = 2048 chunks -> 8 per thread
#pragma unroll
    for (int i = 0; i < 8; i++) {
        const int idx_ = t + i * 256;
        const int r_ = idx_ >> 4;
        const int c_ = (idx_ & 15) << 2;
        cp16(smbase + (QP_OFF + r_ * 68 + c_) * 4, qb + (size_t)r_ * HD_ + c_);
    }
    F_ISSUE(0);
    CP_COMMIT();          // group 0: Q + tile0
    F_ISSUE(1);
    CP_COMMIT();          // group 1: tile1
    CP_WAIT(1);           // Q + tile0 resident
    __syncthreads();

    uint32_t qf[8][4];
#pragma unroll
    for (int kc = 0; kc < 8; kc++) {
        qf[kc][0] = QP[(qm + g) * 68 + kc * 8 + tig];
        qf[kc][1] = QP[(qm + g + 8) * 68 + kc * 8 + tig];
        qf[kc][2] = QP[(qm + g) * 68 + kc * 8 + tig + 4];
        qf[kc][3] = QP[(qm + g + 8) * 68 + kc * 8 + tig + 4];
    }

    float o[8][4];
#pragma unroll
    for (int nt = 0; nt < 8; nt++)
#pragma unroll
        for (int r = 0; r < 4; r++) o[nt][r] = 0.f;
    float m0 = -1e30f, m1 = -1e30f, l0 = 0.f, l1 = 0.f;

    const int NT = S_ / 64;   // 32
    for (int tt = 0; tt < NT; tt++) {
        if (tt > 0) {
            CP_WAIT(1);        // tile tt resident
            __syncthreads();   // stage tt-1 reads done by all warps
        }
        if (tt + 2 < NT) F_ISSUE(tt + 2);
        CP_COMMIT();

        const int st = tt % 3;
        const uint32_t* Kb = smu + KS_OFF + st * 4352;
        const uint32_t* Vb = smu + VT_OFF + st * 4352;
        const float*    Mb = (const float*)(smu + MSK_OFF + st * 64);

        // S = Q @ K^T
        float s[8][4];
#pragma unroll
        for (int nt = 0; nt < 8; nt++)
#pragma unroll
            for (int r = 0; r < 4; r++) s[nt][r] = 0.f;
#pragma unroll
        for (int kc = 0; kc < 8; kc++) {
#pragma unroll
            for (int nt = 0; nt < 8; nt++) {
                uint32_t b0 = Kb[(nt * 8 + g) * 68 + kc * 8 + tig];
                uint32_t b1 = Kb[(nt * 8 + g) * 68 + kc * 8 + tig + 4];
                mma_tf32(s[nt], qf[kc][0], qf[kc][1], qf[kc][2], qf[kc][3], b0, b1);
            }
        }

        // base-2 online softmax; thread owns rows g, g+8 of warp tile
        float rmax0 = -1e30f, rmax1 = -1e30f;
#pragma unroll
        for (int nt = 0; nt < 8; nt++) {
            const float2 mm = *(const float2*)&Mb[nt * 8 + tig * 2];
            const float madd0 = (1.0f - mm.x) * (-10000.0f * LOG2E);
            const float madd1 = (1.0f - mm.y) * (-10000.0f * LOG2E);
            s[nt][0] = fmaf(s[nt][0], SCL, madd0);
            s[nt][1] = fmaf(s[nt][1], SCL, madd1);
            s[nt][2] = fmaf(s[nt][2], SCL, madd0);
            s[nt][3] = fmaf(s[nt][3], SCL, madd1);
            rmax0 = fmaxf(rmax0, fmaxf(s[nt][0], s[nt][1]));
            rmax1 = fmaxf(rmax1, fmaxf(s[nt][2], s[nt][3]));
        }
#pragma unroll
        for (int off = 1; off < 4; off <<= 1) {
            rmax0 = fmaxf(rmax0, __shfl_xor_sync(0xffffffffu, rmax0, off));
            rmax1 = fmaxf(rmax1, __shfl_xor_sync(0xffffffffu, rmax1, off));
        }
        const float m0n = fmaxf(m0, rmax0);
        const float m1n = fmaxf(m1, rmax1);
        const float c0  = ex2(m0 - m0n);
        const float c1  = ex2(m1 - m1n);
        float rs0 = 0.f, rs1 = 0.f;
#pragma unroll
        for (int nt = 0; nt < 8; nt++) {
            s[nt][0] = ex2(s[nt][0] - m0n);
            s[nt][1] = ex2(s[nt][1] - m0n);
            s[nt][2] = ex2(s[nt][2] - m1n);
            s[nt][3] = ex2(s[nt][3] - m1n);
            rs0 += s[nt][0] + s[nt][1];
            rs1 += s[nt][2] + s[nt][3];
        }
#pragma unroll
        for (int off = 1; off < 4; off <<= 1) {
            rs0 += __shfl_xor_sync(0xffffffffu, rs0, off);
            rs1 += __shfl_xor_sync(0xffffffffu, rs1, off);
        }
        l0 = l0 * c0 + rs0;  m0 = m0n;
        l1 = l1 * c1 + rs1;  m1 = m1n;
#pragma unroll
        for (int nt = 0; nt < 8; nt++) {
            o[nt][0] *= c0; o[nt][1] *= c0;
            o[nt][2] *= c1; o[nt][3] *= c1;
        }

        // P -> warp-private rows of QP (tf32)
#pragma unroll
        for (int nt = 0; nt < 8; nt++) {
            *(uint2*)&QP[(qm + g) * 68 + nt * 8 + tig * 2] =
                make_uint2(f2tf(s[nt][0]), f2tf(s[nt][1]));
            *(uint2*)&QP[(qm + g + 8) * 68 + nt * 8 + tig * 2] =
                make_uint2(f2tf(s[nt][2]), f2tf(s[nt][3]));
        }
        __syncwarp();

        // O += P @ V
#pragma unroll
        for (int kc = 0; kc < 8; kc++) {
            uint32_t pa0 = QP[(qm + g) * 68 + kc * 8 + tig];
            uint32_t pa1 = QP[(qm + g + 8) * 68 + kc * 8 + tig];
            uint32_t pa2 = QP[(qm + g) * 68 + kc * 8 + tig + 4];
            uint32_t pa3 = QP[(qm + g + 8) * 68 + kc * 8 + tig + 4];
#pragma unroll
            for (int nt = 0; nt < 8; nt++) {
                uint32_t b0 = Vb[(nt * 8 + g) * 68 + kc * 8 + tig];
                uint32_t b1 = Vb[(nt * 8 + g) * 68 + kc * 8 + tig + 4];
                mma_tf32(o[nt], pa0, pa1, pa2, pa3, b0, b1);
            }
        }
        // P anti-dependency: QP rows are warp-private; next write is after
        // this warp's reads (in-order within warp) and after __syncwarp.
    }
#undef F_ISSUE

    // epilogue: ctx[b][q][h*64+d] = O / l  (tf32 for the O-projection)
    const float inv0 = 1.0f / l0;
    const float inv1 = 1.0f / l1;
    const int r0 = q0 + qm + g;
    const int r1 = r0 + 8;
#pragma unroll
    for (int nt = 0; nt < 8; nt++) {
        const int col = h * HD_ + nt * 8 + tig * 2;
        *(uint2*)&ctx[((size_t)b * S_ + r0) * H_ + col] =
            make_uint2(f2tf(o[nt][0] * inv0), f2tf(o[nt][1] * inv0));
        *(uint2*)&ctx[((size_t)b * S_ + r1) * H_ + col] =
            make_uint2(f2tf(o[nt][2] * inv1), f2tf(o[nt][3] * inv1));
    }
}

// ---------------------------------------------------------------------------
extern "C" void kernel_launch(void* const* d_in, const int* in_sizes, int n_in,
                              void* d_out, int out_size) {
    const float* query = (const float*)d_in[0];
    const float* key_  = (const float*)d_in[1];
    const float* value = (const float*)d_in[2];
    const float* amask = (const float*)d_in[3];
    const float* Wq = (const float*)d_in[4];
    const float* bq = (const float*)d_in[5];
    const float* Wk = (const float*)d_in[6];
    const float* bk = (const float*)d_in[7];
    const float* Wv = (const float*)d_in[8];
    const float* bv = (const float*)d_in[9];
    const float* Wo = (const float*)d_in[10];
    const float* bo = (const float*)d_in[11];
    float* out = (float*)d_out;

    uint32_t *xq, *xk, *xv, *wq, *wk, *wv, *wo, *qp, *kp, *vp, *cp;
    cudaGetSymbolAddress((void**)&xq, g_xq);
    cudaGetSymbolAddress((void**)&xk, g_xk);
    cudaGetSymbolAddress((void**)&xv, g_xv);
    cudaGetSymbolAddress((void**)&wq, g_wq);
    cudaGetSymbolAddress((void**)&wk, g_wk);
    cudaGetSymbolAddress((void**)&wv, g_wv);
    cudaGetSymbolAddress((void**)&wo, g_wo);
    cudaGetSymbolAddress((void**)&qp, g_q);
    cudaGetSymbolAddress((void**)&kp, g_k);
    cudaGetSymbolAddress((void**)&vp, g_v);
    cudaGetSymbolAddress((void**)&cp, g_ctx);

    cudaFuncSetAttribute(gemm3<0>, cudaFuncAttributeMaxDynamicSharedMemorySize, GEMM_SMEM);
    cudaFuncSetAttribute(gemm3<1>, cudaFuncAttributeMaxDynamicSharedMemorySize, GEMM_SMEM);
    cudaFuncSetAttribute(flash_attn_tc3, cudaFuncAttributeMaxDynamicSharedMemorySize, ATTN_SMEM);

    // merged prepass (7 jobs)
    CvtBatch cb;
    cb.s[0] = (const float4*)query; cb.d[0] = (uint4*)xq; cb.n4[0] = M_ * K_ / 4;
    cb.s[1] = (const float4*)key_;  cb.d[1] = (uint4*)xk; cb.n4[1] = M_ * K_ / 4;
    cb.s[2] = (const float4*)value; cb.d[2] = (uint4*)xv; cb.n4[2] = M_ * K_ / 4;
    cb.s[3] = (const float4*)Wq;    cb.d[3] = (uint4*)wq; cb.n4[3] = N_ * K_ / 4;
    cb.s[4] = (const float4*)Wk;    cb.d[4] = (uint4*)wk; cb.n4[4] = N_ * K_ / 4;
    cb.s[5] = (const float4*)Wv;    cb.d[5] = (uint4*)wv; cb.n4[5] = N_ * K_ / 4;
    cb.s[6] = (const float4*)Wo;    cb.d[6] = (uint4*)wo; cb.n4[6] = N_ * K_ / 4;
    cvt7_kernel<<<dim3(592, 1, 7), 256>>>(cb);

    // merged QKV projections
    GemmBatch gqkv;
    gqkv.A[0] = xq; gqkv.W[0] = wq; gqkv.bias[0] = bq; gqkv.C[0] = qp;
    gqkv.A[1] = xk; gqkv.W[1] = wk; gqkv.bias[1] = bk; gqkv.C[1] = kp;
    gqkv.A[2] = xv; gqkv.W[2] = wv; gqkv.bias[2] = bv; gqkv.C[2] = vp;
    gemm3<1><<<dim3(N_ / 128, M_ / 128, 3), 256, GEMM_SMEM>>>(gqkv);

    flash_attn_tc3<<<dim3(S_ / 128, NH_, B_), 256, ATTN_SMEM>>>(qp, kp, vp, amask, cp);

    GemmBatch go;
    go.A[0] = cp; go.W[0] = wo; go.bias[0] = bo; go.C[0] = (uint32_t*)out;
    go.A[1] = go.A[2] = nullptr; go.W[1] = go.W[2] = nullptr;
    go.bias[1] = go.bias[2] = nullptr; go.C[1] = go.C[2] = nullptr;
    gemm3<0><<<dim3(N_ / 128, M_ / 128, 1), 256, GEMM_SMEM>>>(go);
}

// round 6
// speedup vs baseline: 3.3467x; 1.0160x over previous
#include <cuda_runtime.h>
#include <cuda_bf16.h>
#include <math.h>
#include <stdint.h>

#define B_  4
#define S_  2048
#define H_  1024
#define NH_ 16
#define HD_ 64
#define M_  (B_ * S_)
#define K_  1024
#define N_  1024

#define LOG2E 1.4426950408889634f
#define SCL   0.18033688011112042f   // 0.125 * log2(e)

// Scratch (device globals; allocation-free per harness rules)
__device__ uint32_t g_xq[M_ * K_];
__device__ uint32_t g_xk[M_ * K_];
__device__ uint32_t g_xv[M_ * K_];
__device__ uint32_t g_wq[N_ * K_];
__device__ uint32_t g_wk[N_ * K_];
__device__ uint32_t g_wv[N_ * K_];
__device__ uint32_t g_wo[N_ * K_];
__device__ uint32_t g_q[B_ * S_ * H_];    // tf32 [B,NH,S,HD]
__device__ uint32_t g_k[B_ * S_ * H_];    // tf32 [B,NH,S,HD]
__device__ uint32_t g_v[B_ * S_ * H_];    // tf32 [B,NH,HD,S]  (transposed)
__device__ uint32_t g_ctx[B_ * S_ * H_];  // tf32 [B,S,H]

// ---------------------------------------------------------------------------
__device__ __forceinline__ uint32_t f2tf(float f) {
    uint32_t u;
    asm("cvt.rna.tf32.f32 %0, %1;" : "=r"(u) : "f"(f));
    return u;
}
__device__ __forceinline__ float ex2(float x) {
    float y;
    asm("ex2.approx.ftz.f32 %0, %1;" : "=f"(y) : "f"(x));
    return y;
}
__device__ __forceinline__ void mma_tf32(float c[4],
                                         uint32_t a0, uint32_t a1,
                                         uint32_t a2, uint32_t a3,
                                         uint32_t b0, uint32_t b1) {
    asm volatile(
        "mma.sync.aligned.m16n8k8.row.col.f32.tf32.tf32.f32 "
        "{%0,%1,%2,%3},{%4,%5,%6,%7},{%8,%9},{%0,%1,%2,%3};"
        : "+f"(c[0]), "+f"(c[1]), "+f"(c[2]), "+f"(c[3])
        : "r"(a0), "r"(a1), "r"(a2), "r"(a3), "r"(b0), "r"(b1));
}
__device__ __forceinline__ void cp16(uint32_t smem, const void* g) {
    asm volatile("cp.async.cg.shared.global [%0], [%1], 16;" :: "r"(smem), "l"(g));
}
#define CP_COMMIT() asm volatile("cp.async.commit_group;")
#define CP_WAIT(N)  asm volatile("cp.async.wait_group %0;" :: "n"(N))

// ---------------------------------------------------------------------------
// Merged prepass: fp32 -> tf32 (rna), 7 jobs via blockIdx.z
// ---------------------------------------------------------------------------
struct CvtBatch {
    const float4* s[7];
    uint4*        d[7];
    int           n4[7];
};
__global__ void cvt7_kernel(CvtBatch cb) {
    const int z = blockIdx.z;
    const float4* __restrict__ src = cb.s[z];
    uint4* __restrict__ dst = cb.d[z];
    const int n4 = cb.n4[z];
    int i = blockIdx.x * blockDim.x + threadIdx.x;
    const int stride = gridDim.x * blockDim.x;
    for (; i < n4; i += stride) {
        float4 v = src[i];
        dst[i] = make_uint4(f2tf(v.x), f2tf(v.y), f2tf(v.z), f2tf(v.w));
    }
}

// ---------------------------------------------------------------------------
// GEMM: C = A @ W^T + bias (tf32 in). 128x128x16 tiles, 128 threads (4 warps),
// warp tile 64x64 (4 m-tiles x 8 n-tiles), 3-stage cp.async, 1 barrier/k-iter.
// ---------------------------------------------------------------------------
struct GemmBatch {
    const uint32_t* A[3];
    const uint32_t* W[3];
    const float*    bias[3];
    uint32_t*       C[3];
};
#define GSM_STAGE 2560              // 128*20 u32 per stage per matrix
#define GEMM_SMEM (2 * 3 * GSM_STAGE * 4)

template <int QKV>
__global__ __launch_bounds__(128, 2)
void gemm3(GemmBatch gb) {
    extern __shared__ uint32_t smu[];
    uint32_t* smA = smu;
    uint32_t* smW = smu + 3 * GSM_STAGE;

    const int z = QKV ? blockIdx.z : 0;
    const uint32_t* __restrict__ A = gb.A[z];
    const uint32_t* __restrict__ W = gb.W[z];
    const float*    __restrict__ bias = gb.bias[z];
    uint32_t* __restrict__ C = gb.C[z];

    const int t    = threadIdx.x;
    const int warp = t >> 5;
    const int lane = t & 31;
    const int g    = lane >> 2;
    const int tig  = lane & 3;
    const int wm   = (warp & 1) * 64;
    const int wn   = (warp >> 1) * 64;
    const int row0 = blockIdx.y * 128;
    const int col0 = blockIdx.x * 128;

    const uint32_t* Ap = A + (size_t)row0 * K_;
    const uint32_t* Wp = W + (size_t)col0 * K_;
    const uint32_t smA0 = (uint32_t)__cvta_generic_to_shared(smA);
    const uint32_t smW0 = (uint32_t)__cvta_generic_to_shared(smW);

    // staging: 512 16B-chunks per matrix per stage -> 4/thread
    //   idx = t + i*128: r = idx>>2 (0..127), c = (idx&3)*4
#define G_ISSUE(tt) do {                                                        \
        const int st_ = (tt) % 3;                                               \
        const int k0_ = (tt) * 16;                                              \
        _Pragma("unroll")                                                       \
        for (int i = 0; i < 4; i++) {                                           \
            const int idx_ = t + i * 128;                                       \
            const int r_ = idx_ >> 2;                                           \
            const int c_ = (idx_ & 3) << 2;                                     \
            cp16(smA0 + (st_ * GSM_STAGE + r_ * 20 + c_) * 4,                   \
                 Ap + (size_t)r_ * K_ + k0_ + c_);                              \
            cp16(smW0 + (st_ * GSM_STAGE + r_ * 20 + c_) * 4,                   \
                 Wp + (size_t)r_ * K_ + k0_ + c_);                              \
        }                                                                       \
    } while (0)

    float acc[4][8][4];
#pragma unroll
    for (int i = 0; i < 4; i++)
#pragma unroll
        for (int j = 0; j < 8; j++)
#pragma unroll
            for (int r = 0; r < 4; r++) acc[i][j][r] = 0.f;

    G_ISSUE(0); CP_COMMIT();
    G_ISSUE(1); CP_COMMIT();

    const int NT = K_ / 16;   // 64
    for (int tt = 0; tt < NT; tt++) {
        CP_WAIT(1);            // stage tt resident
        __syncthreads();       // visible block-wide; stage tt-1 reads done
        if (tt + 2 < NT) G_ISSUE(tt + 2);
        CP_COMMIT();

        const uint32_t* Ab = smA + (tt % 3) * GSM_STAGE;
        const uint32_t* Wb = smW + (tt % 3) * GSM_STAGE;
#pragma unroll
        for (int kk = 0; kk < 16; kk += 8) {
            uint32_t af[4][4], bf[8][2];
#pragma unroll
            for (int mt = 0; mt < 4; mt++) {
                const int mr = wm + mt * 16;
                af[mt][0] = Ab[(mr + g) * 20 + kk + tig];
                af[mt][1] = Ab[(mr + g + 8) * 20 + kk + tig];
                af[mt][2] = Ab[(mr + g) * 20 + kk + tig + 4];
                af[mt][3] = Ab[(mr + g + 8) * 20 + kk + tig + 4];
            }
#pragma unroll
            for (int nt = 0; nt < 8; nt++) {
                const int nr = wn + nt * 8;
                bf[nt][0] = Wb[(nr + g) * 20 + kk + tig];
                bf[nt][1] = Wb[(nr + g) * 20 + kk + tig + 4];
            }
#pragma unroll
            for (int mt = 0; mt < 4; mt++)
#pragma unroll
                for (int nt = 0; nt < 8; nt++)
                    mma_tf32(acc[mt][nt], af[mt][0], af[mt][1], af[mt][2], af[mt][3],
                             bf[nt][0], bf[nt][1]);
        }
    }
#undef G_ISSUE

#pragma unroll
    for (int mt = 0; mt < 4; mt++) {
#pragma unroll
        for (int half = 0; half < 2; half++) {
            const int row = row0 + wm + mt * 16 + g + half * 8;
#pragma unroll
            for (int nt = 0; nt < 8; nt++) {
                const int col = col0 + wn + nt * 8 + tig * 2;
                const float vx = acc[mt][nt][half * 2 + 0] + bias[col + 0];
                const float vy = acc[mt][nt][half * 2 + 1] + bias[col + 1];
                const int bb = row >> 11, ss = row & 2047;
                const int hh = col >> 6,  dd = col & 63;
                if (!QKV) {
                    *(float2*)&((float*)C)[(size_t)row * N_ + col] = make_float2(vx, vy);
                } else if (z < 2) {
                    *(uint2*)&C[(((size_t)(bb * NH_ + hh) * S_) + ss) * HD_ + dd] =
                        make_uint2(f2tf(vx), f2tf(vy));
                } else {
                    const size_t base = ((size_t)(bb * NH_ + hh) * HD_ + dd) * S_ + ss;
                    C[base]      = f2tf(vx);
                    C[base + S_] = f2tf(vy);
                }
            }
        }
    }
}

// ---------------------------------------------------------------------------
// Flash attention: q-tile 256, 256 threads (8 warps, warp = 32 q-rows = 2
// m-tiles), kv-tile 64, triple-buffered K/V via cp.async, 1 barrier/kv-iter.
// Q/K tf32 [B,NH,S,HD]; V tf32 [B,NH,HD,S].
// smem u32: QP[256][68] | Ks[3][64][68] | Vt[3][64][68] | Msk[3][64]
// ---------------------------------------------------------------------------
#define QP_OFF   0
#define KS_OFF   17408
#define VT_OFF   30464
#define MSK_OFF  43520
#define ATTN_SMEM ((43520 + 192) * 4)   // 174,848 B

__global__ __launch_bounds__(256)
void flash_attn_tc4(const uint32_t* __restrict__ Q, const uint32_t* __restrict__ Kk,
                    const uint32_t* __restrict__ V, const float* __restrict__ amask,
                    uint32_t* __restrict__ ctx) {
    extern __shared__ uint32_t smu[];
    uint32_t* QP = smu + QP_OFF;     // [256][68]
    const uint32_t smbase = (uint32_t)__cvta_generic_to_shared(smu);

    const int t    = threadIdx.x;
    const int warp = t >> 5;
    const int lane = t & 31;
    const int g    = lane >> 2;
    const int tig  = lane & 3;
    const int qm   = warp * 32;        // warp q-row base (0..224)
    const int b    = blockIdx.z;
    const int h    = blockIdx.y;
    const int q0   = blockIdx.x * 256;

    const uint32_t* qb = Q  + ((size_t)(b * NH_ + h) * S_ + q0) * HD_;
    const uint32_t* kb = Kk + ((size_t)(b * NH_ + h) * S_) * HD_;
    const uint32_t* vb = V  + ((size_t)(b * NH_ + h) * HD_) * S_;
    const float*    mb = amask + (size_t)b * S_;

    // K/V tile: 64x64 u32 = 1024 chunks -> 4/thread
#define F_ISSUE(tt) do {                                                          \
        const int st_ = (tt) % 3;                                                 \
        const int kv_ = (tt) * 64;                                                \
        _Pragma("unroll")                                                         \
        for (int i = 0; i < 4; i++) {                                             \
            const int idx_ = t + i * 256;                                         \
            const int r_ = idx_ >> 4;                                             \
            const int c_ = (idx_ & 15) << 2;                                      \
            cp16(smbase + (KS_OFF + st_ * 4352 + r_ * 68 + c_) * 4,               \
                 kb + (size_t)(kv_ + r_) * HD_ + c_);                             \
            cp16(smbase + (VT_OFF + st_ * 4352 + r_ * 68 + c_) * 4,               \
                 vb + (size_t)r_ * S_ + kv_ + c_);                                \
        }                                                                         \
        if (t < 16)                                                               \
            cp16(smbase + (MSK_OFF + st_ * 64 + t * 4) * 4, mb + kv_ + t * 4);    \
    } while (0)

    // prologue: Q tile 256x64 u32 = 4096 chunks -> 16/thread
#pragma unroll
    for (int i = 0; i < 16; i++) {
        const int idx_ = t + i * 256;
        const int r_ = idx_ >> 4;
        const int c_ = (idx_ & 15) << 2;
        cp16(smbase + (QP_OFF + r_ * 68 + c_) * 4, qb + (size_t)r_ * HD_ + c_);
    }
    F_ISSUE(0);
    CP_COMMIT();          // group 0: Q + tile0
    F_ISSUE(1);
    CP_COMMIT();          // group 1: tile1
    CP_WAIT(1);           // Q + tile0 resident
    __syncthreads();

    uint32_t qf[2][8][4];
#pragma unroll
    for (int mt = 0; mt < 2; mt++) {
        const int mr = qm + mt * 16;
#pragma unroll
        for (int kc = 0; kc < 8; kc++) {
            qf[mt][kc][0] = QP[(mr + g) * 68 + kc * 8 + tig];
            qf[mt][kc][1] = QP[(mr + g + 8) * 68 + kc * 8 + tig];
            qf[mt][kc][2] = QP[(mr + g) * 68 + kc * 8 + tig + 4];
            qf[mt][kc][3] = QP[(mr + g + 8) * 68 + kc * 8 + tig + 4];
        }
    }

    float o[2][8][4];
#pragma unroll
    for (int mt = 0; mt < 2; mt++)
#pragma unroll
        for (int nt = 0; nt < 8; nt++)
#pragma unroll
            for (int r = 0; r < 4; r++) o[mt][nt][r] = 0.f;
    float mstat[2][2], lstat[2][2];
#pragma unroll
    for (int mt = 0; mt < 2; mt++) {
        mstat[mt][0] = mstat[mt][1] = -1e30f;
        lstat[mt][0] = lstat[mt][1] = 0.f;
    }

    const int NT = S_ / 64;   // 32
    for (int tt = 0; tt < NT; tt++) {
        if (tt > 0) {
            CP_WAIT(1);        // tile tt resident
            __syncthreads();   // stage tt-1 reads done by all warps
        }
        if (tt + 2 < NT) F_ISSUE(tt + 2);
        CP_COMMIT();

        const int st = tt % 3;
        const uint32_t* Kb = smu + KS_OFF + st * 4352;
        const uint32_t* Vb = smu + VT_OFF + st * 4352;
        const float*    Mb = (const float*)(smu + MSK_OFF + st * 64);

        // per m-tile: S = Q@K^T, softmax, P -> smem
#pragma unroll
        for (int mt = 0; mt < 2; mt++) {
            float s[8][4];
#pragma unroll
            for (int nt = 0; nt < 8; nt++)
#pragma unroll
                for (int r = 0; r < 4; r++) s[nt][r] = 0.f;
#pragma unroll
            for (int kc = 0; kc < 8; kc++) {
#pragma unroll
                for (int nt = 0; nt < 8; nt++) {
                    uint32_t b0 = Kb[(nt * 8 + g) * 68 + kc * 8 + tig];
                    uint32_t b1 = Kb[(nt * 8 + g) * 68 + kc * 8 + tig + 4];
                    mma_tf32(s[nt], qf[mt][kc][0], qf[mt][kc][1],
                             qf[mt][kc][2], qf[mt][kc][3], b0, b1);
                }
            }

            float rmax0 = -1e30f, rmax1 = -1e30f;
#pragma unroll
            for (int nt = 0; nt < 8; nt++) {
                const float2 mm = *(const float2*)&Mb[nt * 8 + tig * 2];
                const float madd0 = (1.0f - mm.x) * (-10000.0f * LOG2E);
                const float madd1 = (1.0f - mm.y) * (-10000.0f * LOG2E);
                s[nt][0] = fmaf(s[nt][0], SCL, madd0);
                s[nt][1] = fmaf(s[nt][1], SCL, madd1);
                s[nt][2] = fmaf(s[nt][2], SCL, madd0);
                s[nt][3] = fmaf(s[nt][3], SCL, madd1);
                rmax0 = fmaxf(rmax0, fmaxf(s[nt][0], s[nt][1]));
                rmax1 = fmaxf(rmax1, fmaxf(s[nt][2], s[nt][3]));
            }
#pragma unroll
            for (int off = 1; off < 4; off <<= 1) {
                rmax0 = fmaxf(rmax0, __shfl_xor_sync(0xffffffffu, rmax0, off));
                rmax1 = fmaxf(rmax1, __shfl_xor_sync(0xffffffffu, rmax1, off));
            }
            const float m0n = fmaxf(mstat[mt][0], rmax0);
            const float m1n = fmaxf(mstat[mt][1], rmax1);
            const float c0  = ex2(mstat[mt][0] - m0n);
            const float c1  = ex2(mstat[mt][1] - m1n);
            float rs0 = 0.f, rs1 = 0.f;
#pragma unroll
            for (int nt = 0; nt < 8; nt++) {
                s[nt][0] = ex2(s[nt][0] - m0n);
                s[nt][1] = ex2(s[nt][1] - m0n);
                s[nt][2] = ex2(s[nt][2] - m1n);
                s[nt][3] = ex2(s[nt][3] - m1n);
                rs0 += s[nt][0] + s[nt][1];
                rs1 += s[nt][2] + s[nt][3];
            }
#pragma unroll
            for (int off = 1; off < 4; off <<= 1) {
                rs0 += __shfl_xor_sync(0xffffffffu, rs0, off);
                rs1 += __shfl_xor_sync(0xffffffffu, rs1, off);
            }
            lstat[mt][0] = lstat[mt][0] * c0 + rs0;  mstat[mt][0] = m0n;
            lstat[mt][1] = lstat[mt][1] * c1 + rs1;  mstat[mt][1] = m1n;
#pragma unroll
            for (int nt = 0; nt < 8; nt++) {
                o[mt][nt][0] *= c0; o[mt][nt][1] *= c0;
                o[mt][nt][2] *= c1; o[mt][nt][3] *= c1;
            }

            const int mr = qm + mt * 16;
#pragma unroll
            for (int nt = 0; nt < 8; nt++) {
                *(uint2*)&QP[(mr + g) * 68 + nt * 8 + tig * 2] =
                    make_uint2(f2tf(s[nt][0]), f2tf(s[nt][1]));
                *(uint2*)&QP[(mr + g + 8) * 68 + nt * 8 + tig * 2] =
                    make_uint2(f2tf(s[nt][2]), f2tf(s[nt][3]));
            }
        }
        __syncwarp();

        // O += P @ V  (both m-tiles; B-frags shared)
#pragma unroll
        for (int kc = 0; kc < 8; kc++) {
            uint32_t pa[2][4];
#pragma unroll
            for (int mt = 0; mt < 2; mt++) {
                const int mr = qm + mt * 16;
                pa[mt][0] = QP[(mr + g) * 68 + kc * 8 + tig];
                pa[mt][1] = QP[(mr + g + 8) * 68 + kc * 8 + tig];
                pa[mt][2] = QP[(mr + g) * 68 + kc * 8 + tig + 4];
                pa[mt][3] = QP[(mr + g + 8) * 68 + kc * 8 + tig + 4];
            }
#pragma unroll
            for (int nt = 0; nt < 8; nt++) {
                uint32_t b0 = Vb[(nt * 8 + g) * 68 + kc * 8 + tig];
                uint32_t b1 = Vb[(nt * 8 + g) * 68 + kc * 8 + tig + 4];
                mma_tf32(o[0][nt], pa[0][0], pa[0][1], pa[0][2], pa[0][3], b0, b1);
                mma_tf32(o[1][nt], pa[1][0], pa[1][1], pa[1][2], pa[1][3], b0, b1);
            }
        }
        // P anti-dependency: QP rows warp-private; in-order within warp.
    }
#undef F_ISSUE

    // epilogue: ctx[b][q][h*64+d] = O / l  (tf32 for the O-projection)
#pragma unroll
    for (int mt = 0; mt < 2; mt++) {
        const float inv0 = 1.0f / lstat[mt][0];
        const float inv1 = 1.0f / lstat[mt][1];
        const int r0 = q0 + qm + mt * 16 + g;
        const int r1 = r0 + 8;
#pragma unroll
        for (int nt = 0; nt < 8; nt++) {
            const int col = h * HD_ + nt * 8 + tig * 2;
            *(uint2*)&ctx[((size_t)b * S_ + r0) * H_ + col] =
                make_uint2(f2tf(o[mt][nt][0] * inv0), f2tf(o[mt][nt][1] * inv0));
            *(uint2*)&ctx[((size_t)b * S_ + r1) * H_ + col] =
                make_uint2(f2tf(o[mt][nt][2] * inv1), f2tf(o[mt][nt][3] * inv1));
        }
    }
}

// ---------------------------------------------------------------------------
extern "C" void kernel_launch(void* const* d_in, const int* in_sizes, int n_in,
                              void* d_out, int out_size) {
    const float* query = (const float*)d_in[0];
    const float* key_  = (const float*)d_in[1];
    const float* value = (const float*)d_in[2];
    const float* amask = (const float*)d_in[3];
    const float* Wq = (const float*)d_in[4];
    const float* bq = (const float*)d_in[5];
    const float* Wk = (const float*)d_in[6];
    const float* bk = (const float*)d_in[7];
    const float* Wv = (const float*)d_in[8];
    const float* bv = (const float*)d_in[9];
    const float* Wo = (const float*)d_in[10];
    const float* bo = (const float*)d_in[11];
    float* out = (float*)d_out;

    uint32_t *xq, *xk, *xv, *wq, *wk, *wv, *wo, *qp, *kp, *vp, *cp;
    cudaGetSymbolAddress((void**)&xq, g_xq);
    cudaGetSymbolAddress((void**)&xk, g_xk);
    cudaGetSymbolAddress((void**)&xv, g_xv);
    cudaGetSymbolAddress((void**)&wq, g_wq);
    cudaGetSymbolAddress((void**)&wk, g_wk);
    cudaGetSymbolAddress((void**)&wv, g_wv);
    cudaGetSymbolAddress((void**)&wo, g_wo);
    cudaGetSymbolAddress((void**)&qp, g_q);
    cudaGetSymbolAddress((void**)&kp, g_k);
    cudaGetSymbolAddress((void**)&vp, g_v);
    cudaGetSymbolAddress((void**)&cp, g_ctx);

    cudaFuncSetAttribute(gemm3<0>, cudaFuncAttributeMaxDynamicSharedMemorySize, GEMM_SMEM);
    cudaFuncSetAttribute(gemm3<1>, cudaFuncAttributeMaxDynamicSharedMemorySize, GEMM_SMEM);
    cudaFuncSetAttribute(flash_attn_tc4, cudaFuncAttributeMaxDynamicSharedMemorySize, ATTN_SMEM);

    // merged prepass (7 jobs)
    CvtBatch cb;
    cb.s[0] = (const float4*)query; cb.d[0] = (uint4*)xq; cb.n4[0] = M_ * K_ / 4;
    cb.s[1] = (const float4*)key_;  cb.d[1] = (uint4*)xk; cb.n4[1] = M_ * K_ / 4;
    cb.s[2] = (const float4*)value; cb.d[2] = (uint4*)xv; cb.n4[2] = M_ * K_ / 4;
    cb.s[3] = (const float4*)Wq;    cb.d[3] = (uint4*)wq; cb.n4[3] = N_ * K_ / 4;
    cb.s[4] = (const float4*)Wk;    cb.d[4] = (uint4*)wk; cb.n4[4] = N_ * K_ / 4;
    cb.s[5] = (const float4*)Wv;    cb.d[5] = (uint4*)wv; cb.n4[5] = N_ * K_ / 4;
    cb.s[6] = (const float4*)Wo;    cb.d[6] = (uint4*)wo; cb.n4[6] = N_ * K_ / 4;
    cvt7_kernel<<<dim3(592, 1, 7), 256>>>(cb);

    // merged QKV projections
    GemmBatch gqkv;
    gqkv.A[0] = xq; gqkv.W[0] = wq; gqkv.bias[0] = bq; gqkv.C[0] = qp;
    gqkv.A[1] = xk; gqkv.W[1] = wk; gqkv.bias[1] = bk; gqkv.C[1] = kp;
    gqkv.A[2] = xv; gqkv.W[2] = wv; gqkv.bias[2] = bv; gqkv.C[2] = vp;
    gemm3<1><<<dim3(N_ / 128, M_ / 128, 3), 128, GEMM_SMEM>>>(gqkv);

    flash_attn_tc4<<<dim3(S_ / 256, NH_, B_), 256, ATTN_SMEM>>>(qp, kp, vp, amask, cp);

    GemmBatch go;
    go.A[0] = cp; go.W[0] = wo; go.bias[0] = bo; go.C[0] = (uint32_t*)out;
    go.A[1] = go.A[2] = nullptr; go.W[1] = go.W[2] = nullptr;
    go.bias[1] = go.bias[2] = nullptr; go.C[1] = go.C[2] = nullptr;
    gemm3<0><<<dim3(N_ / 128, M_ / 128, 1), 128, GEMM_SMEM>>>(go);
}

// round 9
// speedup vs baseline: 6.4859x; 1.9380x over previous
#include <cuda_runtime.h>
#include <cuda_bf16.h>
#include <cuda_fp16.h>
#include <math.h>
#include <stdint.h>

#define B_  4
#define S_  2048
#define H_  1024
#define NH_ 16
#define HD_ 64
#define M_  (B_ * S_)
#define K_  1024
#define N_  1024
#define KW_ (K_ / 2)    // 512 u32 words per row (half2-packed)

#define LOG2E 1.4426950408889634f
#define SCL   0.18033688011112042f   // 0.125 * log2(e)

// Scratch (device globals; allocation-free). All half2-packed (u32 words).
__device__ uint32_t g_xq[M_ * KW_];
__device__ uint32_t g_xk[M_ * KW_];
__device__ uint32_t g_xv[M_ * KW_];
__device__ uint32_t g_wq[N_ * KW_];
__device__ uint32_t g_wk[N_ * KW_];
__device__ uint32_t g_wv[N_ * KW_];
__device__ uint32_t g_wo[N_ * KW_];
__device__ uint32_t g_q[B_ * S_ * H_ / 2];    // fp16 [B,NH,S,HD]
__device__ uint32_t g_k[B_ * S_ * H_ / 2];    // fp16 [B,NH,S,HD]
__device__ uint32_t g_v[B_ * S_ * H_ / 2];    // fp16 [B,NH,HD,S] (transposed)
__device__ uint32_t g_ctx[B_ * S_ * H_ / 2];  // fp16 [B,S,H]

// ---------------------------------------------------------------------------
__device__ __forceinline__ uint32_t packh2(float a, float b) {
    __half2 h = __floats2half2_rn(a, b);   // low = a, high = b
    return *(uint32_t*)&h;
}
__device__ __forceinline__ float ex2(float x) {
    float y;
    asm("ex2.approx.ftz.f32 %0, %1;" : "=f"(y) : "f"(x));
    return y;
}
__device__ __forceinline__ void mma_f16(float c[4],
                                        uint32_t a0, uint32_t a1,
                                        uint32_t a2, uint32_t a3,
                                        uint32_t b0, uint32_t b1) {
    asm volatile(
        "mma.sync.aligned.m16n8k16.row.col.f32.f16.f16.f32 "
        "{%0,%1,%2,%3},{%4,%5,%6,%7},{%8,%9},{%0,%1,%2,%3};"
        : "+f"(c[0]), "+f"(c[1]), "+f"(c[2]), "+f"(c[3])
        : "r"(a0), "r"(a1), "r"(a2), "r"(a3), "r"(b0), "r"(b1));
}
__device__ __forceinline__ void cp16(uint32_t smem, const void* g) {
    asm volatile("cp.async.cg.shared.global [%0], [%1], 16;" :: "r"(smem), "l"(g));
}
#define CP_COMMIT() asm volatile("cp.async.commit_group;")
#define CP_WAIT(N)  asm volatile("cp.async.wait_group %0;" :: "n"(N))

// ---------------------------------------------------------------------------
// Merged prepass: fp32 -> fp16 (rn), 7 jobs via blockIdx.z. 8 floats/iter.
// ---------------------------------------------------------------------------
struct CvtBatch {
    const float4* s[7];
    uint4*        d[7];
    int           n8[7];
};
__global__ void cvt7_kernel(CvtBatch cb) {
    const int z = blockIdx.z;
    const float4* __restrict__ src = cb.s[z];
    uint4* __restrict__ dst = cb.d[z];
    const int n8 = cb.n8[z];
    int i = blockIdx.x * blockDim.x + threadIdx.x;
    const int stride = gridDim.x * blockDim.x;
    for (; i < n8; i += stride) {
        float4 v0 = src[2 * i];
        float4 v1 = src[2 * i + 1];
        uint4 o;
        o.x = packh2(v0.x, v0.y);
        o.y = packh2(v0.z, v0.w);
        o.z = packh2(v1.x, v1.y);
        o.w = packh2(v1.z, v1.w);
        dst[i] = o;
    }
}

// ---------------------------------------------------------------------------
// GEMM: C = A @ W^T + bias (fp16 in, fp32 accum). 128x128 tile, BK=32 halves
// (16 words), 128 threads (4 warps, warp tile 64x64), 3-stage cp.async,
// one barrier per k-iter.
// smem words: [0..127] bias f32 | A stages @128 (3x2560) | B stages @7808
// ---------------------------------------------------------------------------
struct GemmBatch {
    const uint32_t* A[3];
    const uint32_t* W[3];
    const float*    bias[3];
    uint32_t*       C[3];
};
#define GSTG  2560                      // 128 rows * 20 words
#define SMA0  128
#define SMB0  (128 + 3 * GSTG)
#define GEMM_SMEM ((128 + 6 * GSTG) * 4)   // 61,952 B -> 2 CTAs/SM

template <int QKV>
__global__ __launch_bounds__(128, 2)
void gemm_h(GemmBatch gb) {
    extern __shared__ uint32_t smu[];
    const uint32_t smb = (uint32_t)__cvta_generic_to_shared(smu);
    float* sbias = (float*)smu;

    const int z = QKV ? blockIdx.z : 0;
    const uint32_t* __restrict__ A = gb.A[z];
    const uint32_t* __restrict__ W = gb.W[z];
    const float*    __restrict__ bias = gb.bias[z];
    uint32_t* __restrict__ C = gb.C[z];

    const int t    = threadIdx.x;
    const int warp = t >> 5;
    const int lane = t & 31;
    const int g    = lane >> 2;
    const int tig  = lane & 3;
    const int wm   = (warp & 1) * 64;
    const int wn   = (warp >> 1) * 64;
    const int row0 = blockIdx.y * 128;
    const int col0 = blockIdx.x * 128;

    const uint32_t* Ap = A + (size_t)row0 * KW_;
    const uint32_t* Wp = W + (size_t)col0 * KW_;

    sbias[t] = bias[col0 + t];   // 128 threads, 128 cols

    // stage fill: 128 rows x 16 words = 512 chunks per matrix -> 4/thread
    //   idx = t + i*128: r = idx>>2 (0..127), cw = (idx&3)*4 (0,4,8,12)
#define G_ISSUE(tt) do {                                                        \
        const int st_ = (tt) % 3;                                               \
        const int k0w_ = (tt) * 16;                                             \
        _Pragma("unroll")                                                       \
        for (int i_ = 0; i_ < 4; i_++) {                                        \
            const int idx_ = t + i_ * 128;                                      \
            const int r_ = idx_ >> 2;                                           \
            const int cw_ = (idx_ & 3) << 2;                                    \
            cp16(smb + (SMA0 + st_ * GSTG + r_ * 20 + cw_) * 4,                 \
                 Ap + (size_t)r_ * KW_ + k0w_ + cw_);                           \
            cp16(smb + (SMB0 + st_ * GSTG + r_ * 20 + cw_) * 4,                 \
                 Wp + (size_t)r_ * KW_ + k0w_ + cw_);                           \
        }                                                                       \
    } while (0)

    float acc[4][8][4];
#pragma unroll
    for (int i = 0; i < 4; i++)
#pragma unroll
        for (int j = 0; j < 8; j++)
#pragma unroll
            for (int r = 0; r < 4; r++) acc[i][j][r] = 0.f;

    G_ISSUE(0); CP_COMMIT();
    G_ISSUE(1); CP_COMMIT();

    const int NT = KW_ / 16;   // 32 iters of 32 halves
    for (int tt = 0; tt < NT; tt++) {
        CP_WAIT(1);
        __syncthreads();
        if (tt + 2 < NT) G_ISSUE(tt + 2);
        CP_COMMIT();

        const uint32_t* Ab = smu + SMA0 + (tt % 3) * GSTG;
        const uint32_t* Wb = smu + SMB0 + (tt % 3) * GSTG;
#pragma unroll
        for (int kkw = 0; kkw < 16; kkw += 8) {   // two k16 chunks
            uint32_t af[4][4], bf[8][2];
#pragma unroll
            for (int mt = 0; mt < 4; mt++) {
                const int mr = wm + mt * 16;
                af[mt][0] = Ab[(mr + g) * 20 + kkw + tig];
                af[mt][1] = Ab[(mr + g + 8) * 20 + kkw + tig];
                af[mt][2] = Ab[(mr + g) * 20 + kkw + tig + 4];
                af[mt][3] = Ab[(mr + g + 8) * 20 + kkw + tig + 4];
            }
#pragma unroll
            for (int nt = 0; nt < 8; nt++) {
                const int nr = wn + nt * 8;
                bf[nt][0] = Wb[(nr + g) * 20 + kkw + tig];
                bf[nt][1] = Wb[(nr + g) * 20 + kkw + tig + 4];
            }
#pragma unroll
            for (int mt = 0; mt < 4; mt++)
#pragma unroll
                for (int nt = 0; nt < 8; nt++)
                    mma_f16(acc[mt][nt], af[mt][0], af[mt][1], af[mt][2], af[mt][3],
                            bf[nt][0], bf[nt][1]);
        }
    }
#undef G_ISSUE

    // epilogue (C-frag layout: rows g,g+8; cols tig*2,tig*2+1)
#pragma unroll
    for (int mt = 0; mt < 4; mt++) {
#pragma unroll
        for (int half = 0; half < 2; half++) {
            const int row = row0 + wm + mt * 16 + g + half * 8;
#pragma unroll
            for (int nt = 0; nt < 8; nt++) {
                const int col = col0 + wn + nt * 8 + tig * 2;
                const float vx = acc[mt][nt][half * 2 + 0] + sbias[wn + nt * 8 + tig * 2 + 0];
                const float vy = acc[mt][nt][half * 2 + 1] + sbias[wn + nt * 8 + tig * 2 + 1];
                const int bb = row >> 11, ss = row & 2047;
                const int hh = col >> 6,  dd = col & 63;
                if (!QKV) {
                    *(float2*)&((float*)C)[(size_t)row * N_ + col] = make_float2(vx, vy);
                } else if (z < 2) {
                    // [B,NH,S,HD] half: pair (dd,dd+1) -> one half2 word
                    C[(((size_t)(bb * NH_ + hh) * S_) + ss) * (HD_ / 2) + (dd >> 1)] =
                        packh2(vx, vy);
                } else {
                    // [B,NH,HD,S] half: rows dd,dd+1 at col ss -> 2 half stores
                    __half* Ch = (__half*)C;
                    const size_t base = ((size_t)(bb * NH_ + hh) * HD_ + dd) * S_ + ss;
                    Ch[base]      = __float2half_rn(vx);
                    Ch[base + S_] = __float2half_rn(vy);
                }
            }
        }
    }
}

// ---------------------------------------------------------------------------
// Flash attention, fp16 MMA: q-tile 128, 256 threads (8 warps, warp = 16
// q-rows), kv-tile 64, triple-buffered cp.async, 1 barrier/kv-iter, 2 CTAs/SM.
// Q/K fp16 [B,NH,S,HD]; V fp16 [B,NH,HD,S].
// smem words: QP[128][36] | Ks[3][64][36] | Vt[3][64][36] | Msk[3][64]f32
// ---------------------------------------------------------------------------
#define QP_OFF   0
#define KS_OFF   4608
#define VT_OFF   11520
#define MSK_OFF  18432
#define FSTG     2304                  // 64*36
#define ATTN_SMEM ((18432 + 192) * 4)  // 74,496 B -> 2 CTAs/SM

__global__ __launch_bounds__(256, 2)
void flash_attn_h(const uint32_t* __restrict__ Q, const uint32_t* __restrict__ Kk,
                  const uint32_t* __restrict__ V, const float* __restrict__ amask,
                  uint32_t* __restrict__ ctx) {
    extern __shared__ uint32_t smu[];
    uint32_t* QP = smu + QP_OFF;       // [128][36]
    const uint32_t smbase = (uint32_t)__cvta_generic_to_shared(smu);

    const int t    = threadIdx.x;
    const int warp = t >> 5;
    const int lane = t & 31;
    const int g    = lane >> 2;
    const int tig  = lane & 3;
    const int qm   = warp * 16;        // warp q-row base (0..112)
    const int b    = blockIdx.z;
    const int h    = blockIdx.y;
    const int q0   = blockIdx.x * 128;

    const uint32_t* qb = Q  + ((size_t)(b * NH_ + h) * S_ + q0) * (HD_ / 2);
    const uint32_t* kb = Kk + ((size_t)(b * NH_ + h) * S_) * (HD_ / 2);
    const uint32_t* vb = V  + ((size_t)(b * NH_ + h) * HD_) * (S_ / 2);
    const float*    mb = amask + (size_t)b * S_;

    // K/V tile: 64 rows x 32 words = 512 chunks -> 2/thread
#define F_ISSUE(tt) do {                                                          \
        const int st_ = (tt) % 3;                                                 \
        const int kvw_ = (tt) * 32;     /* kv offset in words */                  \
        _Pragma("unroll")                                                         \
        for (int i = 0; i < 2; i++) {                                             \
            const int idx_ = t + i * 256;                                         \
            const int r_ = idx_ >> 3;                                             \
            const int cw_ = (idx_ & 7) << 2;                                      \
            cp16(smbase + (KS_OFF + st_ * FSTG + r_ * 36 + cw_) * 4,              \
                 kb + (size_t)((tt) * 64 + r_) * (HD_ / 2) + cw_);                \
            cp16(smbase + (VT_OFF + st_ * FSTG + r_ * 36 + cw_) * 4,              \
                 vb + (size_t)r_ * (S_ / 2) + kvw_ + cw_);                        \
        }                                                                         \
        if (t < 16)                                                               \
            cp16(smbase + (MSK_OFF + st_ * 64 + t * 4) * 4, mb + (tt) * 64 + t * 4); \
    } while (0)

    // prologue: Q tile 128 rows x 32 words = 1024 chunks -> 4/thread
#pragma unroll
    for (int i = 0; i < 4; i++) {
        const int idx_ = t + i * 256;
        const int r_ = idx_ >> 3;
        const int cw_ = (idx_ & 7) << 2;
        cp16(smbase + (QP_OFF + r_ * 36 + cw_) * 4, qb + (size_t)r_ * (HD_ / 2) + cw_);
    }
    F_ISSUE(0);
    CP_COMMIT();          // group 0: Q + tile0
    F_ISSUE(1);
    CP_COMMIT();          // group 1: tile1
    CP_WAIT(1);
    __syncthreads();

    // Q fragments: 4 k16-chunks x 4 regs
    uint32_t qf[4][4];
#pragma unroll
    for (int kc = 0; kc < 4; kc++) {
        qf[kc][0] = QP[(qm + g) * 36 + kc * 8 + tig];
        qf[kc][1] = QP[(qm + g + 8) * 36 + kc * 8 + tig];
        qf[kc][2] = QP[(qm + g) * 36 + kc * 8 + tig + 4];
        qf[kc][3] = QP[(qm + g + 8) * 36 + kc * 8 + tig + 4];
    }

    float o[8][4];
#pragma unroll
    for (int nt = 0; nt < 8; nt++)
#pragma unroll
        for (int r = 0; r < 4; r++) o[nt][r] = 0.f;
    float m0 = -1e30f, m1 = -1e30f, l0 = 0.f, l1 = 0.f;

    const int NT = S_ / 64;   // 32
    for (int tt = 0; tt < NT; tt++) {
        if (tt > 0) {
            CP_WAIT(1);
            __syncthreads();
        }
        if (tt + 2 < NT) F_ISSUE(tt + 2);
        CP_COMMIT();

        const int st = tt % 3;
        const uint32_t* Kb = smu + KS_OFF + st * FSTG;
        const uint32_t* Vb = smu + VT_OFF + st * FSTG;
        const float*    Mb = (const float*)(smu + MSK_OFF + st * 64);

        // S = Q @ K^T  (B operand = Ks[kv][d], n = kv)
        float s[8][4];
#pragma unroll
        for (int nt = 0; nt < 8; nt++)
#pragma unroll
            for (int r = 0; r < 4; r++) s[nt][r] = 0.f;
#pragma unroll
        for (int kc = 0; kc < 4; kc++) {
#pragma unroll
            for (int nt = 0; nt < 8; nt++) {
                uint32_t b0 = Kb[(nt * 8 + g) * 36 + kc * 8 + tig];
                uint32_t b1 = Kb[(nt * 8 + g) * 36 + kc * 8 + tig + 4];
                mma_f16(s[nt], qf[kc][0], qf[kc][1], qf[kc][2], qf[kc][3], b0, b1);
            }
        }

        // base-2 online softmax; thread owns rows g, g+8 of warp tile
        float rmax0 = -1e30f, rmax1 = -1e30f;
#pragma unroll
        for (int nt = 0; nt < 8; nt++) {
            const float2 mm = *(const float2*)&Mb[nt * 8 + tig * 2];
            const float madd0 = (1.0f - mm.x) * (-10000.0f * LOG2E);
            const float madd1 = (1.0f - mm.y) * (-10000.0f * LOG2E);
            s[nt][0] = fmaf(s[nt][0], SCL, madd0);
            s[nt][1] = fmaf(s[nt][1], SCL, madd1);
            s[nt][2] = fmaf(s[nt][2], SCL, madd0);
            s[nt][3] = fmaf(s[nt][3], SCL, madd1);
            rmax0 = fmaxf(rmax0, fmaxf(s[nt][0], s[nt][1]));
            rmax1 = fmaxf(rmax1, fmaxf(s[nt][2], s[nt][3]));
        }
#pragma unroll
        for (int off = 1; off < 4; off <<= 1) {
            rmax0 = fmaxf(rmax0, __shfl_xor_sync(0xffffffffu, rmax0, off));
            rmax1 = fmaxf(rmax1, __shfl_xor_sync(0xffffffffu, rmax1, off));
        }
        const float m0n = fmaxf(m0, rmax0);
        const float m1n = fmaxf(m1, rmax1);
        const float c0  = ex2(m0 - m0n);
        const float c1  = ex2(m1 - m1n);
        float rs0 = 0.f, rs1 = 0.f;
#pragma unroll
        for (int nt = 0; nt < 8; nt++) {
            s[nt][0] = ex2(s[nt][0] - m0n);
            s[nt][1] = ex2(s[nt][1] - m0n);
            s[nt][2] = ex2(s[nt][2] - m1n);
            s[nt][3] = ex2(s[nt][3] - m1n);
            rs0 += s[nt][0] + s[nt][1];
            rs1 += s[nt][2] + s[nt][3];
        }
#pragma unroll
        for (int off = 1; off < 4; off <<= 1) {
            rs0 += __shfl_xor_sync(0xffffffffu, rs0, off);
            rs1 += __shfl_xor_sync(0xffffffffu, rs1, off);
        }
        l0 = l0 * c0 + rs0;  m0 = m0n;
        l1 = l1 * c1 + rs1;  m1 = m1n;
#pragma unroll
        for (int nt = 0; nt < 8; nt++) {
            o[nt][0] *= c0; o[nt][1] *= c0;
            o[nt][2] *= c1; o[nt][3] *= c1;
        }

        // P -> warp-private rows of QP (half2: kv pair -> one word)
#pragma unroll
        for (int nt = 0; nt < 8; nt++) {
            QP[(qm + g) * 36 + nt * 4 + tig]     = packh2(s[nt][0], s[nt][1]);
            QP[(qm + g + 8) * 36 + nt * 4 + tig] = packh2(s[nt][2], s[nt][3]);
        }
        __syncwarp();

        // O += P @ V  (contraction over kv: 4 k16-chunks)
#pragma unroll
        for (int kc = 0; kc < 4; kc++) {
            uint32_t pa0 = QP[(qm + g) * 36 + kc * 8 + tig];
            uint32_t pa1 = QP[(qm + g + 8) * 36 + kc * 8 + tig];
            uint32_t pa2 = QP[(qm + g) * 36 + kc * 8 + tig + 4];
            uint32_t pa3 = QP[(qm + g + 8) * 36 + kc * 8 + tig + 4];
#pragma unroll
            for (int nt = 0; nt < 8; nt++) {
                uint32_t b0 = Vb[(nt * 8 + g) * 36 + kc * 8 + tig];
                uint32_t b1 = Vb[(nt * 8 + g) * 36 + kc * 8 + tig + 4];
                mma_f16(o[nt], pa0, pa1, pa2, pa3, b0, b1);
            }
        }
        // P anti-dependency: QP rows warp-private; in-order within warp.
    }
#undef F_ISSUE

    // epilogue: ctx[b][q][h*64+d] = O / l  (half2 words)
    const float inv0 = 1.0f / l0;
    const float inv1 = 1.0f / l1;
    const int r0 = q0 + qm + g;
    const int r1 = r0 + 8;
#pragma unroll
    for (int nt = 0; nt < 8; nt++) {
        const int col = h * HD_ + nt * 8 + tig * 2;
        ctx[((size_t)b * S_ + r0) * (H_ / 2) + (col >> 1)] =
            packh2(o[nt][0] * inv0, o[nt][1] * inv0);
        ctx[((size_t)b * S_ + r1) * (H_ / 2) + (col >> 1)] =
            packh2(o[nt][2] * inv1, o[nt][3] * inv1);
    }
}

// ---------------------------------------------------------------------------
extern "C" void kernel_launch(void* const* d_in, const int* in_sizes, int n_in,
                              void* d_out, int out_size) {
    const float* query = (const float*)d_in[0];
    const float* key_  = (const float*)d_in[1];
    const float* value = (const float*)d_in[2];
    const float* amask = (const float*)d_in[3];
    const float* Wq = (const float*)d_in[4];
    const float* bq = (const float*)d_in[5];
    const float* Wk = (const float*)d_in[6];
    const float* bk = (const float*)d_in[7];
    const float* Wv = (const float*)d_in[8];
    const float* bv = (const float*)d_in[9];
    const float* Wo = (const float*)d_in[10];
    const float* bo = (const float*)d_in[11];
    float* out = (float*)d_out;

    uint32_t *xq, *xk, *xv, *wq, *wk, *wv, *wo, *qp, *kp, *vp, *cp;
    cudaGetSymbolAddress((void**)&xq, g_xq);
    cudaGetSymbolAddress((void**)&xk, g_xk);
    cudaGetSymbolAddress((void**)&xv, g_xv);
    cudaGetSymbolAddress((void**)&wq, g_wq);
    cudaGetSymbolAddress((void**)&wk, g_wk);
    cudaGetSymbolAddress((void**)&wv, g_wv);
    cudaGetSymbolAddress((void**)&wo, g_wo);
    cudaGetSymbolAddress((void**)&qp, g_q);
    cudaGetSymbolAddress((void**)&kp, g_k);
    cudaGetSymbolAddress((void**)&vp, g_v);
    cudaGetSymbolAddress((void**)&cp, g_ctx);

    cudaFuncSetAttribute(gemm_h<0>, cudaFuncAttributeMaxDynamicSharedMemorySize, GEMM_SMEM);
    cudaFuncSetAttribute(gemm_h<1>, cudaFuncAttributeMaxDynamicSharedMemorySize, GEMM_SMEM);
    cudaFuncSetAttribute(flash_attn_h, cudaFuncAttributeMaxDynamicSharedMemorySize, ATTN_SMEM);

    // merged prepass (7 jobs), fp32 -> fp16
    CvtBatch cb;
    cb.s[0] = (const float4*)query; cb.d[0] = (uint4*)xq; cb.n8[0] = M_ * K_ / 8;
    cb.s[1] = (const float4*)key_;  cb.d[1] = (uint4*)xk; cb.n8[1] = M_ * K_ / 8;
    cb.s[2] = (const float4*)value; cb.d[2] = (uint4*)xv; cb.n8[2] = M_ * K_ / 8;
    cb.s[3] = (const float4*)Wq;    cb.d[3] = (uint4*)wq; cb.n8[3] = N_ * K_ / 8;
    cb.s[4] = (const float4*)Wk;    cb.d[4] = (uint4*)wk; cb.n8[4] = N_ * K_ / 8;
    cb.s[5] = (const float4*)Wv;    cb.d[5] = (uint4*)wv; cb.n8[5] = N_ * K_ / 8;
    cb.s[6] = (const float4*)Wo;    cb.d[6] = (uint4*)wo; cb.n8[6] = N_ * K_ / 8;
    cvt7_kernel<<<dim3(296, 1, 7), 256>>>(cb);

    // merged QKV projections
    GemmBatch gqkv;
    gqkv.A[0] = xq; gqkv.W[0] = wq; gqkv.bias[0] = bq; gqkv.C[0] = qp;
    gqkv.A[1] = xk; gqkv.W[1] = wk; gqkv.bias[1] = bk; gqkv.C[1] = kp;
    gqkv.A[2] = xv; gqkv.W[2] = wv; gqkv.bias[2] = bv; gqkv.C[2] = vp;
    gemm_h<1><<<dim3(N_ / 128, M_ / 128, 3), 128, GEMM_SMEM>>>(gqkv);

    flash_attn_h<<<dim3(S_ / 128, NH_, B_), 256, ATTN_SMEM>>>(qp, kp, vp, amask, cp);

    GemmBatch go;
    go.A[0] = cp; go.W[0] = wo; go.bias[0] = bo; go.C[0] = (uint32_t*)out;
    go.A[1] = go.A[2] = nullptr; go.W[1] = go.W[2] = nullptr;
    go.bias[1] = go.bias[2] = nullptr; go.C[1] = go.C[2] = nullptr;
    gemm_h<0><<<dim3(N_ / 128, M_ / 128, 1), 128, GEMM_SMEM>>>(go);
}

// round 10
// speedup vs baseline: 7.2620x; 1.1197x over previous
#include <cuda_runtime.h>
#include <cuda_bf16.h>
#include <cuda_fp16.h>
#include <math.h>
#include <stdint.h>

#define B_  4
#define S_  2048
#define H_  1024
#define NH_ 16
#define HD_ 64
#define M_  (B_ * S_)
#define K_  1024
#define N_  1024
#define KW_ (K_ / 2)    // 512 u32 words per row (half2-packed)

#define LOG2E 1.4426950408889634f
#define SCL   0.18033688011112042f   // 0.125 * log2(e)

// Scratch (device globals; allocation-free). All half2-packed (u32 words).
__device__ uint32_t g_xq[M_ * KW_];
__device__ uint32_t g_xk[M_ * KW_];
__device__ uint32_t g_xv[M_ * KW_];
__device__ uint32_t g_wq[N_ * KW_];
__device__ uint32_t g_wk[N_ * KW_];
__device__ uint32_t g_wv[N_ * KW_];
__device__ uint32_t g_wo[N_ * KW_];
__device__ uint32_t g_q[B_ * S_ * H_ / 2];    // fp16 [B,NH,S,HD]
__device__ uint32_t g_k[B_ * S_ * H_ / 2];    // fp16 [B,NH,S,HD]
__device__ uint32_t g_v[B_ * S_ * H_ / 2];    // fp16 [B,NH,HD,S] (transposed)
__device__ uint32_t g_ctx[B_ * S_ * H_ / 2];  // fp16 [B,S,H]

// ---------------------------------------------------------------------------
__device__ __forceinline__ uint32_t packh2(float a, float b) {
    __half2 h = __floats2half2_rn(a, b);   // low = a, high = b
    return *(uint32_t*)&h;
}
__device__ __forceinline__ float ex2(float x) {
    float y;
    asm("ex2.approx.ftz.f32 %0, %1;" : "=f"(y) : "f"(x));
    return y;
}
__device__ __forceinline__ void mma_f16(float c[4],
                                        uint32_t a0, uint32_t a1,
                                        uint32_t a2, uint32_t a3,
                                        uint32_t b0, uint32_t b1) {
    asm volatile(
        "mma.sync.aligned.m16n8k16.row.col.f32.f16.f16.f32 "
        "{%0,%1,%2,%3},{%4,%5,%6,%7},{%8,%9},{%0,%1,%2,%3};"
        : "+f"(c[0]), "+f"(c[1]), "+f"(c[2]), "+f"(c[3])
        : "r"(a0), "r"(a1), "r"(a2), "r"(a3), "r"(b0), "r"(b1));
}
__device__ __forceinline__ void ldsm4(uint32_t& r0, uint32_t& r1,
                                      uint32_t& r2, uint32_t& r3, uint32_t addr) {
    asm volatile("ldmatrix.sync.aligned.m8n8.x4.shared.b16 {%0,%1,%2,%3}, [%4];"
                 : "=r"(r0), "=r"(r1), "=r"(r2), "=r"(r3) : "r"(addr));
}
__device__ __forceinline__ void cp16(uint32_t smem, const void* g) {
    asm volatile("cp.async.cg.shared.global [%0], [%1], 16;" :: "r"(smem), "l"(g));
}
#define CP_COMMIT() asm volatile("cp.async.commit_group;")
#define CP_WAIT(N)  asm volatile("cp.async.wait_group %0;" :: "n"(N))

// ---------------------------------------------------------------------------
// Merged prepass: fp32 -> fp16 (rn), 7 jobs via blockIdx.z. 8 floats/iter.
// ---------------------------------------------------------------------------
struct CvtBatch {
    const float4* s[7];
    uint4*        d[7];
    int           n8[7];
};
__global__ void cvt7_kernel(CvtBatch cb) {
    const int z = blockIdx.z;
    const float4* __restrict__ src = cb.s[z];
    uint4* __restrict__ dst = cb.d[z];
    const int n8 = cb.n8[z];
    int i = blockIdx.x * blockDim.x + threadIdx.x;
    const int stride = gridDim.x * blockDim.x;
    for (; i < n8; i += stride) {
        float4 v0 = src[2 * i];
        float4 v1 = src[2 * i + 1];
        uint4 o;
        o.x = packh2(v0.x, v0.y);
        o.y = packh2(v0.z, v0.w);
        o.z = packh2(v1.x, v1.y);
        o.w = packh2(v1.z, v1.w);
        dst[i] = o;
    }
}

// ---------------------------------------------------------------------------
// GEMM: C = A @ W^T + bias (fp16 in, fp32 accum). 128x128 tile, BK=32 halves
// (16 words), 128 threads (4 warps, warp tile 64x64), 3-stage cp.async,
// one barrier per k-iter, ldmatrix fragment loads.
// ---------------------------------------------------------------------------
struct GemmBatch {
    const uint32_t* A[3];
    const uint32_t* W[3];
    const float*    bias[3];
    uint32_t*       C[3];
};
#define GSTG  2560                      // 128 rows * 20 words
#define SMA0  128
#define SMB0  (128 + 3 * GSTG)
#define GEMM_SMEM ((128 + 6 * GSTG) * 4)   // 61,952 B -> 2 CTAs/SM

template <int QKV>
__global__ __launch_bounds__(128, 2)
void gemm_h(GemmBatch gb) {
    extern __shared__ uint32_t smu[];
    const uint32_t smb = (uint32_t)__cvta_generic_to_shared(smu);
    float* sbias = (float*)smu;

    const int z = QKV ? blockIdx.z : 0;
    const uint32_t* __restrict__ A = gb.A[z];
    const uint32_t* __restrict__ W = gb.W[z];
    const float*    __restrict__ bias = gb.bias[z];
    uint32_t* __restrict__ C = gb.C[z];

    const int t    = threadIdx.x;
    const int warp = t >> 5;
    const int lane = t & 31;
    const int g    = lane >> 2;
    const int tig  = lane & 3;
    const int wm   = (warp & 1) * 64;
    const int wn   = (warp >> 1) * 64;
    const int row0 = blockIdx.y * 128;
    const int col0 = blockIdx.x * 128;

    // ldmatrix per-lane octet decode
    const int l8   = lane & 7;
    const int arow = l8 + ((lane >> 3) & 1) * 8;    // A/P: oct&1 -> +8 rows
    const int acol = ((lane >> 4) & 1) * 4;         //      oct&2 -> +4 words
    const int brow = l8 + ((lane >> 4) & 1) * 8;    // B: oct&2 -> +8 rows
    const int bcol = ((lane >> 3) & 1) * 4;         //    oct&1 -> +4 words

    const uint32_t* Ap = A + (size_t)row0 * KW_;
    const uint32_t* Wp = W + (size_t)col0 * KW_;

    sbias[t] = bias[col0 + t];   // 128 threads, 128 cols

    // stage fill: 128 rows x 16 words = 512 chunks per matrix -> 4/thread
#define G_ISSUE(tt) do {                                                        \
        const int st_ = (tt) % 3;                                               \
        const int k0w_ = (tt) * 16;                                             \
        _Pragma("unroll")                                                       \
        for (int i_ = 0; i_ < 4; i_++) {                                        \
            const int idx_ = t + i_ * 128;                                      \
            const int r_ = idx_ >> 2;                                           \
            const int cw_ = (idx_ & 3) << 2;                                    \
            cp16(smb + (SMA0 + st_ * GSTG + r_ * 20 + cw_) * 4,                 \
                 Ap + (size_t)r_ * KW_ + k0w_ + cw_);                           \
            cp16(smb + (SMB0 + st_ * GSTG + r_ * 20 + cw_) * 4,                 \
                 Wp + (size_t)r_ * KW_ + k0w_ + cw_);                           \
        }                                                                       \
    } while (0)

    float acc[4][8][4];
#pragma unroll
    for (int i = 0; i < 4; i++)
#pragma unroll
        for (int j = 0; j < 8; j++)
#pragma unroll
            for (int r = 0; r < 4; r++) acc[i][j][r] = 0.f;

    G_ISSUE(0); CP_COMMIT();
    G_ISSUE(1); CP_COMMIT();

    const int NT = KW_ / 16;   // 32 iters of 32 halves
    for (int tt = 0; tt < NT; tt++) {
        CP_WAIT(1);
        __syncthreads();
        if (tt + 2 < NT) G_ISSUE(tt + 2);
        CP_COMMIT();

        const uint32_t abase = smb + (SMA0 + (tt % 3) * GSTG) * 4;
        const uint32_t bbase = smb + (SMB0 + (tt % 3) * GSTG) * 4;
#pragma unroll
        for (int kkw = 0; kkw < 16; kkw += 8) {   // two k16 chunks
            uint32_t af[4][4], bf[8][2];
#pragma unroll
            for (int mt = 0; mt < 4; mt++)
                ldsm4(af[mt][0], af[mt][1], af[mt][2], af[mt][3],
                      abase + ((wm + mt * 16 + arow) * 20 + kkw + acol) * 4);
#pragma unroll
            for (int np = 0; np < 4; np++)
                ldsm4(bf[np * 2][0], bf[np * 2][1], bf[np * 2 + 1][0], bf[np * 2 + 1][1],
                      bbase + ((wn + np * 16 + brow) * 20 + kkw + bcol) * 4);
#pragma unroll
            for (int mt = 0; mt < 4; mt++)
#pragma unroll
                for (int nt = 0; nt < 8; nt++)
                    mma_f16(acc[mt][nt], af[mt][0], af[mt][1], af[mt][2], af[mt][3],
                            bf[nt][0], bf[nt][1]);
        }
    }
#undef G_ISSUE

    // epilogue (C-frag layout: rows g,g+8; cols tig*2,tig*2+1)
#pragma unroll
    for (int mt = 0; mt < 4; mt++) {
#pragma unroll
        for (int half = 0; half < 2; half++) {
            const int row = row0 + wm + mt * 16 + g + half * 8;
#pragma unroll
            for (int nt = 0; nt < 8; nt++) {
                const int col = col0 + wn + nt * 8 + tig * 2;
                const float vx = acc[mt][nt][half * 2 + 0] + sbias[wn + nt * 8 + tig * 2 + 0];
                const float vy = acc[mt][nt][half * 2 + 1] + sbias[wn + nt * 8 + tig * 2 + 1];
                const int bb = row >> 11, ss = row & 2047;
                const int hh = col >> 6,  dd = col & 63;
                if (!QKV) {
                    *(float2*)&((float*)C)[(size_t)row * N_ + col] = make_float2(vx, vy);
                } else if (z < 2) {
                    C[(((size_t)(bb * NH_ + hh) * S_) + ss) * (HD_ / 2) + (dd >> 1)] =
                        packh2(vx, vy);
                } else {
                    __half* Ch = (__half*)C;
                    const size_t base = ((size_t)(bb * NH_ + hh) * HD_ + dd) * S_ + ss;
                    Ch[base]      = __float2half_rn(vx);
                    Ch[base + S_] = __float2half_rn(vy);
                }
            }
        }
    }
}

// ---------------------------------------------------------------------------
// Flash attention, fp16 MMA + ldmatrix: q-tile 128, 256 threads (8 warps,
// warp = 16 q-rows), kv-tile 64, triple-buffered cp.async, 2 CTAs/SM.
// Q/K fp16 [B,NH,S,HD]; V fp16 [B,NH,HD,S].
// smem words: QP[128][36] | Ks[3][64][36] | Vt[3][64][36] | Msk[3][64]f32
// ---------------------------------------------------------------------------
#define QP_OFF   0
#define KS_OFF   4608
#define VT_OFF   11520
#define MSK_OFF  18432
#define FSTG     2304                  // 64*36
#define ATTN_SMEM ((18432 + 192) * 4)  // 74,496 B -> 2 CTAs/SM

__global__ __launch_bounds__(256, 2)
void flash_attn_h(const uint32_t* __restrict__ Q, const uint32_t* __restrict__ Kk,
                  const uint32_t* __restrict__ V, const float* __restrict__ amask,
                  uint32_t* __restrict__ ctx) {
    extern __shared__ uint32_t smu[];
    uint32_t* QP = smu + QP_OFF;       // [128][36]
    const uint32_t smbase = (uint32_t)__cvta_generic_to_shared(smu);

    const int t    = threadIdx.x;
    const int warp = t >> 5;
    const int lane = t & 31;
    const int g    = lane >> 2;
    const int tig  = lane & 3;
    const int qm   = warp * 16;        // warp q-row base (0..112)
    const int b    = blockIdx.z;
    const int h    = blockIdx.y;
    const int q0   = blockIdx.x * 128;

    const int l8   = lane & 7;
    const int arow = l8 + ((lane >> 3) & 1) * 8;    // A/P octet decode
    const int acol = ((lane >> 4) & 1) * 4;
    const int brow = l8 + ((lane >> 4) & 1) * 8;    // B octet decode
    const int bcol = ((lane >> 3) & 1) * 4;

    const uint32_t* qb = Q  + ((size_t)(b * NH_ + h) * S_ + q0) * (HD_ / 2);
    const uint32_t* kb = Kk + ((size_t)(b * NH_ + h) * S_) * (HD_ / 2);
    const uint32_t* vb = V  + ((size_t)(b * NH_ + h) * HD_) * (S_ / 2);
    const float*    mb = amask + (size_t)b * S_;

    // K/V tile: 64 rows x 32 words = 512 chunks -> 2/thread
#define F_ISSUE(tt) do {                                                          \
        const int st_ = (tt) % 3;                                                 \
        const int kvw_ = (tt) * 32;     /* kv offset in words */                  \
        _Pragma("unroll")                                                         \
        for (int i = 0; i < 2; i++) {                                             \
            const int idx_ = t + i * 256;                                         \
            const int r_ = idx_ >> 3;                                             \
            const int cw_ = (idx_ & 7) << 2;                                      \
            cp16(smbase + (KS_OFF + st_ * FSTG + r_ * 36 + cw_) * 4,              \
                 kb + (size_t)((tt) * 64 + r_) * (HD_ / 2) + cw_);                \
            cp16(smbase + (VT_OFF + st_ * FSTG + r_ * 36 + cw_) * 4,              \
                 vb + (size_t)r_ * (S_ / 2) + kvw_ + cw_);                        \
        }                                                                         \
        if (t < 16)                                                               \
            cp16(smbase + (MSK_OFF + st_ * 64 + t * 4) * 4, mb + (tt) * 64 + t * 4); \
    } while (0)

    // prologue: Q tile 128 rows x 32 words = 1024 chunks -> 4/thread
#pragma unroll
    for (int i = 0; i < 4; i++) {
        const int idx_ = t + i * 256;
        const int r_ = idx_ >> 3;
        const int cw_ = (idx_ & 7) << 2;
        cp16(smbase + (QP_OFF + r_ * 36 + cw_) * 4, qb + (size_t)r_ * (HD_ / 2) + cw_);
    }
    F_ISSUE(0);
    CP_COMMIT();          // group 0: Q + tile0
    F_ISSUE(1);
    CP_COMMIT();          // group 1: tile1
    CP_WAIT(1);
    __syncthreads();

    // Q fragments: 4 k16-chunks x 4 regs (ldmatrix)
    uint32_t qf[4][4];
#pragma unroll
    for (int kc = 0; kc < 4; kc++)
        ldsm4(qf[kc][0], qf[kc][1], qf[kc][2], qf[kc][3],
              smbase + (QP_OFF + (qm + arow) * 36 + kc * 8 + acol) * 4);

    float o[8][4];
#pragma unroll
    for (int nt = 0; nt < 8; nt++)
#pragma unroll
        for (int r = 0; r < 4; r++) o[nt][r] = 0.f;
    float m0 = -1e30f, m1 = -1e30f, l0 = 0.f, l1 = 0.f;

    const int NT = S_ / 64;   // 32
    for (int tt = 0; tt < NT; tt++) {
        if (tt > 0) {
            CP_WAIT(1);
            __syncthreads();
        }
        if (tt + 2 < NT) F_ISSUE(tt + 2);
        CP_COMMIT();

        const int st = tt % 3;
        const uint32_t kbase = smbase + (KS_OFF + st * FSTG) * 4;
        const uint32_t vbase = smbase + (VT_OFF + st * FSTG) * 4;
        const float*   Mb = (const float*)(smu + MSK_OFF + st * 64);

        // S = Q @ K^T  (B operand = Ks[kv][d], n = kv)
        float s[8][4];
#pragma unroll
        for (int nt = 0; nt < 8; nt++)
#pragma unroll
            for (int r = 0; r < 4; r++) s[nt][r] = 0.f;
#pragma unroll
        for (int kc = 0; kc < 4; kc++) {
            uint32_t bf[8][2];
#pragma unroll
            for (int np = 0; np < 4; np++)
                ldsm4(bf[np * 2][0], bf[np * 2][1], bf[np * 2 + 1][0], bf[np * 2 + 1][1],
                      kbase + ((np * 16 + brow) * 36 + kc * 8 + bcol) * 4);
#pragma unroll
            for (int nt = 0; nt < 8; nt++)
                mma_f16(s[nt], qf[kc][0], qf[kc][1], qf[kc][2], qf[kc][3],
                        bf[nt][0], bf[nt][1]);
        }

        // base-2 online softmax; thread owns rows g, g+8 of warp tile
        float rmax0 = -1e30f, rmax1 = -1e30f;
#pragma unroll
        for (int nt = 0; nt < 8; nt++) {
            const float2 mm = *(const float2*)&Mb[nt * 8 + tig * 2];
            const float madd0 = (1.0f - mm.x) * (-10000.0f * LOG2E);
            const float madd1 = (1.0f - mm.y) * (-10000.0f * LOG2E);
            s[nt][0] = fmaf(s[nt][0], SCL, madd0);
            s[nt][1] = fmaf(s[nt][1], SCL, madd1);
            s[nt][2] = fmaf(s[nt][2], SCL, madd0);
            s[nt][3] = fmaf(s[nt][3], SCL, madd1);
            rmax0 = fmaxf(rmax0, fmaxf(s[nt][0], s[nt][1]));
            rmax1 = fmaxf(rmax1, fmaxf(s[nt][2], s[nt][3]));
        }
#pragma unroll
        for (int off = 1; off < 4; off <<= 1) {
            rmax0 = fmaxf(rmax0, __shfl_xor_sync(0xffffffffu, rmax0, off));
            rmax1 = fmaxf(rmax1, __shfl_xor_sync(0xffffffffu, rmax1, off));
        }
        const float m0n = fmaxf(m0, rmax0);
        const float m1n = fmaxf(m1, rmax1);
        const float c0  = ex2(m0 - m0n);
        const float c1  = ex2(m1 - m1n);
        float rs0 = 0.f, rs1 = 0.f;
#pragma unroll
        for (int nt = 0; nt < 8; nt++) {
            s[nt][0] = ex2(s[nt][0] - m0n);
            s[nt][1] = ex2(s[nt][1] - m0n);
            s[nt][2] = ex2(s[nt][2] - m1n);
            s[nt][3] = ex2(s[nt][3] - m1n);
            rs0 += s[nt][0] + s[nt][1];
            rs1 += s[nt][2] + s[nt][3];
        }
#pragma unroll
        for (int off = 1; off < 4; off <<= 1) {
            rs0 += __shfl_xor_sync(0xffffffffu, rs0, off);
            rs1 += __shfl_xor_sync(0xffffffffu, rs1, off);
        }
        l0 = l0 * c0 + rs0;  m0 = m0n;
        l1 = l1 * c1 + rs1;  m1 = m1n;
#pragma unroll
        for (int nt = 0; nt < 8; nt++) {
            o[nt][0] *= c0; o[nt][1] *= c0;
            o[nt][2] *= c1; o[nt][3] *= c1;
        }

        // P -> warp-private rows of QP (half2: kv pair -> one word)
#pragma unroll
        for (int nt = 0; nt < 8; nt++) {
            QP[(qm + g) * 36 + nt * 4 + tig]     = packh2(s[nt][0], s[nt][1]);
            QP[(qm + g + 8) * 36 + nt * 4 + tig] = packh2(s[nt][2], s[nt][3]);
        }
        __syncwarp();

        // O += P @ V  (contraction over kv: 4 k16-chunks; ldmatrix A + B)
#pragma unroll
        for (int kc = 0; kc < 4; kc++) {
            uint32_t pa0, pa1, pa2, pa3;
            ldsm4(pa0, pa1, pa2, pa3,
                  smbase + (QP_OFF + (qm + arow) * 36 + kc * 8 + acol) * 4);
            uint32_t bf[8][2];
#pragma unroll
            for (int np = 0; np < 4; np++)
                ldsm4(bf[np * 2][0], bf[np * 2][1], bf[np * 2 + 1][0], bf[np * 2 + 1][1],
                      vbase + ((np * 16 + brow) * 36 + kc * 8 + bcol) * 4);
#pragma unroll
            for (int nt = 0; nt < 8; nt++)
                mma_f16(o[nt], pa0, pa1, pa2, pa3, bf[nt][0], bf[nt][1]);
        }
        // P anti-dependency: QP rows warp-private; in-order within warp.
    }
#undef F_ISSUE

    // epilogue: ctx[b][q][h*64+d] = O / l  (half2 words)
    const float inv0 = 1.0f / l0;
    const float inv1 = 1.0f / l1;
    const int r0 = q0 + qm + g;
    const int r1 = r0 + 8;
#pragma unroll
    for (int nt = 0; nt < 8; nt++) {
        const int col = h * HD_ + nt * 8 + tig * 2;
        ctx[((size_t)b * S_ + r0) * (H_ / 2) + (col >> 1)] =
            packh2(o[nt][0] * inv0, o[nt][1] * inv0);
        ctx[((size_t)b * S_ + r1) * (H_ / 2) + (col >> 1)] =
            packh2(o[nt][2] * inv1, o[nt][3] * inv1);
    }
}

// ---------------------------------------------------------------------------
extern "C" void kernel_launch(void* const* d_in, const int* in_sizes, int n_in,
                              void* d_out, int out_size) {
    const float* query = (const float*)d_in[0];
    const float* key_  = (const float*)d_in[1];
    const float* value = (const float*)d_in[2];
    const float* amask = (const float*)d_in[3];
    const float* Wq = (const float*)d_in[4];
    const float* bq = (const float*)d_in[5];
    const float* Wk = (const float*)d_in[6];
    const float* bk = (const float*)d_in[7];
    const float* Wv = (const float*)d_in[8];
    const float* bv = (const float*)d_in[9];
    const float* Wo = (const float*)d_in[10];
    const float* bo = (const float*)d_in[11];
    float* out = (float*)d_out;

    uint32_t *xq, *xk, *xv, *wq, *wk, *wv, *wo, *qp, *kp, *vp, *cp;
    cudaGetSymbolAddress((void**)&xq, g_xq);
    cudaGetSymbolAddress((void**)&xk, g_xk);
    cudaGetSymbolAddress((void**)&xv, g_xv);
    cudaGetSymbolAddress((void**)&wq, g_wq);
    cudaGetSymbolAddress((void**)&wk, g_wk);
    cudaGetSymbolAddress((void**)&wv, g_wv);
    cudaGetSymbolAddress((void**)&wo, g_wo);
    cudaGetSymbolAddress((void**)&qp, g_q);
    cudaGetSymbolAddress((void**)&kp, g_k);
    cudaGetSymbolAddress((void**)&vp, g_v);
    cudaGetSymbolAddress((void**)&cp, g_ctx);

    cudaFuncSetAttribute(gemm_h<0>, cudaFuncAttributeMaxDynamicSharedMemorySize, GEMM_SMEM);
    cudaFuncSetAttribute(gemm_h<1>, cudaFuncAttributeMaxDynamicSharedMemorySize, GEMM_SMEM);
    cudaFuncSetAttribute(flash_attn_h, cudaFuncAttributeMaxDynamicSharedMemorySize, ATTN_SMEM);

    // merged prepass (7 jobs), fp32 -> fp16
    CvtBatch cb;
    cb.s[0] = (const float4*)query; cb.d[0] = (uint4*)xq; cb.n8[0] = M_ * K_ / 8;
    cb.s[1] = (const float4*)key_;  cb.d[1] = (uint4*)xk; cb.n8[1] = M_ * K_ / 8;
    cb.s[2] = (const float4*)value; cb.d[2] = (uint4*)xv; cb.n8[2] = M_ * K_ / 8;
    cb.s[3] = (const float4*)Wq;    cb.d[3] = (uint4*)wq; cb.n8[3] = N_ * K_ / 8;
    cb.s[4] = (const float4*)Wk;    cb.d[4] = (uint4*)wk; cb.n8[4] = N_ * K_ / 8;
    cb.s[5] = (const float4*)Wv;    cb.d[5] = (uint4*)wv; cb.n8[5] = N_ * K_ / 8;
    cb.s[6] = (const float4*)Wo;    cb.d[6] = (uint4*)wo; cb.n8[6] = N_ * K_ / 8;
    cvt7_kernel<<<dim3(296, 1, 7), 256>>>(cb);

    // merged QKV projections
    GemmBatch gqkv;
    gqkv.A[0] = xq; gqkv.W[0] = wq; gqkv.bias[0] = bq; gqkv.C[0] = qp;
    gqkv.A[1] = xk; gqkv.W[1] = wk; gqkv.bias[1] = bk; gqkv.C[1] = kp;
    gqkv.A[2] = xv; gqkv.W[2] = wv; gqkv.bias[2] = bv; gqkv.C[2] = vp;
    gemm_h<1><<<dim3(N_ / 128, M_ / 128, 3), 128, GEMM_SMEM>>>(gqkv);

    flash_attn_h<<<dim3(S_ / 128, NH_, B_), 256, ATTN_SMEM>>>(qp, kp, vp, amask, cp);

    GemmBatch go;
    go.A[0] = cp; go.W[0] = wo; go.bias[0] = bo; go.C[0] = (uint32_t*)out;
    go.A[1] = go.A[2] = nullptr; go.W[1] = go.W[2] = nullptr;
    go.bias[1] = go.bias[2] = nullptr; go.C[1] = go.C[2] = nullptr;
    gemm_h<0><<<dim3(N_ / 128, M_ / 128, 1), 128, GEMM_SMEM>>>(go);
}